// round 3
// baseline (speedup 1.0000x reference)
#include <cuda_runtime.h>
#include <math.h>

// ---------------------------------------------------------------------------
// SPINN shift-reduce TreeLSTM, fp32 SIMT baseline.
//
// Shapes: B=128, L=128, E=512, H=512, T=255, S=L+2=130
// Inputs (metadata order):
//   0 sentence    float [128,128,512]
//   1 transitions int32 [128,255]
//   2 word_W      float [512,1024]
//   3 word_b      float [1024]
//   4 bn_gamma    float [1024]
//   5 bn_beta     float [1024]
//   6 reduce_W    float [1024,2560]
//   7 reduce_b    float [2560]
// Output: float [128,512]
// ---------------------------------------------------------------------------

#define BB 128
#define LL 128
#define EE 512
#define HH 512
#define TT 255
#define SS 130
#define NLE (BB*LL)        // 16384
#define TWO_H 1024
#define FIVE_H 2560

// ------------------------- scratch (static device memory) ------------------
__device__ float g_tmp[NLE * TWO_H];            // word gemm output (pre-BN)   67 MB
__device__ float g_hbuf[BB * LL * HH];          // BN'd h word buffer          33.5 MB
__device__ float g_cbuf[BB * LL * HH];          // BN'd c word buffer          33.5 MB
__device__ float g_stack_h[BB * SS * HH];       // stack h                     34 MB
__device__ float g_stack_c[BB * SS * HH];       // stack c                     34 MB
__device__ float g_x[2][BB * TWO_H];            // double-buffered gather x
__device__ float g_sum[TWO_H];
__device__ float g_sumsq[TWO_H];
__device__ float g_scale[TWO_H];
__device__ float g_shift[TWO_H];
__device__ int   g_i1[TT * BB];
__device__ int   g_i2[TT * BB];
__device__ int   g_pos[TT * BB];
__device__ int   g_bi[TT * BB];
__device__ int   g_flg[TT * BB];                // bit0 = shift, bit1 = write
__device__ int   g_fin[BB];

__device__ __forceinline__ float sigf(float x) { return 1.0f / (1.0f + expf(-x)); }

// ------------------------- phase A: word GEMM -------------------------------
// C[16384][1024] = A[16384][512] @ W[512][1024] + bias
__global__ __launch_bounds__(256) void word_gemm(
    const float* __restrict__ A, const float* __restrict__ W,
    const float* __restrict__ bias)
{
    __shared__ float As[64][33];
    __shared__ float Bs[32][64];
    const int tx = threadIdx.x & 15;        // 0..15 -> 4 cols each
    const int ty = threadIdx.x >> 4;        // 0..15 -> 4 rows each
    const int rowBase = blockIdx.y * 64;
    const int colBase = blockIdx.x * 64;

    float acc[4][4];
#pragma unroll
    for (int i = 0; i < 4; i++)
#pragma unroll
        for (int j = 0; j < 4; j++) acc[i][j] = 0.f;

    for (int k0 = 0; k0 < EE; k0 += 32) {
#pragma unroll
        for (int i = 0; i < 8; i++) {
            int idx = threadIdx.x + i * 256;
            int r = idx >> 5, c = idx & 31;
            As[r][c] = A[(rowBase + r) * EE + k0 + c];
        }
#pragma unroll
        for (int i = 0; i < 8; i++) {
            int idx = threadIdx.x + i * 256;
            int r = idx >> 6, c = idx & 63;
            Bs[r][c] = W[(k0 + r) * TWO_H + colBase + c];
        }
        __syncthreads();
#pragma unroll
        for (int kk = 0; kk < 32; kk++) {
            float a0 = As[ty * 4 + 0][kk];
            float a1 = As[ty * 4 + 1][kk];
            float a2 = As[ty * 4 + 2][kk];
            float a3 = As[ty * 4 + 3][kk];
            float4 b4 = *reinterpret_cast<const float4*>(&Bs[kk][tx * 4]);
            acc[0][0] += a0 * b4.x; acc[0][1] += a0 * b4.y; acc[0][2] += a0 * b4.z; acc[0][3] += a0 * b4.w;
            acc[1][0] += a1 * b4.x; acc[1][1] += a1 * b4.y; acc[1][2] += a1 * b4.z; acc[1][3] += a1 * b4.w;
            acc[2][0] += a2 * b4.x; acc[2][1] += a2 * b4.y; acc[2][2] += a2 * b4.z; acc[2][3] += a2 * b4.w;
            acc[3][0] += a3 * b4.x; acc[3][1] += a3 * b4.y; acc[3][2] += a3 * b4.z; acc[3][3] += a3 * b4.w;
        }
        __syncthreads();
    }
#pragma unroll
    for (int i = 0; i < 4; i++)
#pragma unroll
        for (int j = 0; j < 4; j++) {
            int col = colBase + tx * 4 + j;
            g_tmp[(rowBase + ty * 4 + i) * TWO_H + col] = acc[i][j] + bias[col];
        }
}

// ------------------------- phase A: BatchNorm stats -------------------------
__global__ void zero_stats()
{
    int ch = blockIdx.x * blockDim.x + threadIdx.x;
    if (ch < TWO_H) { g_sum[ch] = 0.f; g_sumsq[ch] = 0.f; }
}

// grid (4 ch-groups of 256, 256 row-chunks of 64), block 256
__global__ __launch_bounds__(256) void bn_stats()
{
    int ch = blockIdx.x * 256 + threadIdx.x;
    int rowBase = blockIdx.y * 64;
    float s = 0.f, q = 0.f;
#pragma unroll 4
    for (int r = 0; r < 64; r++) {
        float v = g_tmp[(rowBase + r) * TWO_H + ch];
        s += v; q += v * v;
    }
    atomicAdd(&g_sum[ch], s);
    atomicAdd(&g_sumsq[ch], q);
}

__global__ void bn_finalize(const float* __restrict__ gamma, const float* __restrict__ beta)
{
    int ch = blockIdx.x * blockDim.x + threadIdx.x;
    if (ch >= TWO_H) return;
    const float invN = 1.0f / (float)NLE;
    float mean = g_sum[ch] * invN;
    float var  = g_sumsq[ch] * invN - mean * mean;
    float sc   = gamma[ch] * rsqrtf(var + 1e-5f);
    g_scale[ch] = sc;
    g_shift[ch] = beta[ch] - mean * sc;
}

__global__ __launch_bounds__(256) void bn_apply()
{
    int idx = blockIdx.x * 256 + threadIdx.x;   // < 16384*1024
    int row = idx >> 10;
    int ch  = idx & 1023;
    float v = g_tmp[idx] * g_scale[ch] + g_shift[ch];
    if (ch < HH) g_hbuf[row * HH + ch] = v;
    else         g_cbuf[row * HH + (ch - HH)] = v;
}

// ------------------------- metadata precompute ------------------------------
__global__ void meta_kernel(const int* __restrict__ trans)
{
    int b = threadIdx.x;
    if (b >= BB) return;
    int ptr = 0, bp = 0;
    for (int t = 0; t < TT; t++) {
        int act = trans[b * TT + t];
        int i1 = min(max(ptr - 1, 0), SS - 1);
        int i2 = min(max(ptr - 2, 0), SS - 1);
        int bi = min(max(bp, 0), LL - 1);
        bool is_s = (act == 2);
        bool is_r = (act == 3);
        int pos = is_s ? min(max(ptr, 0), SS - 1) : i2;
        int flg = (is_s ? 1 : 0) | ((is_s || is_r) ? 2 : 0);
        if (!(is_s || is_r)) pos = -1;   // PAD: never matches, never written
        int o = t * BB + b;
        g_i1[o] = i1; g_i2[o] = i2; g_pos[o] = pos; g_bi[o] = bi; g_flg[o] = flg;
        ptr += is_s ? 1 : (is_r ? -1 : 0);
        bp  += is_s ? 1 : 0;
    }
    g_fin[b] = min(max(ptr - 1, 0), SS - 1);
}

// ------------------------- per-step fused kernel ----------------------------
// grid: x = 32 j-tiles (16 cols), y = 4 b-tiles (32 rows); 256 threads.
// Computes a = x @ reduce_W + b for 5 gates, TreeLSTM, shift/reduce select,
// stack scatter, and next-step x gather (race-free: thread owns column (b,j)).
__global__ __launch_bounds__(256) void step_kernel(
    int t, const float* __restrict__ W, const float* __restrict__ br)
{
    __shared__ float Xs[32][36];   // [b_local][k]   (pad -> 16B-aligned rows)
    __shared__ float Ws[80][36];   // [gate*16+j][k] transposed for float4 k-reads

    const int tid = threadIdx.x;
    const int jl = tid & 15;       // 0..15 hidden col within tile
    const int bl = tid >> 4;       // 0..15 -> handles b_local {bl, bl+16}
    const int jt = blockIdx.x;
    const int bt = blockIdx.y;
    const float* __restrict__ xin = g_x[t & 1];
    float* __restrict__ xout = g_x[(t + 1) & 1];

    float acc[2][5];
#pragma unroll
    for (int s = 0; s < 2; s++)
#pragma unroll
        for (int g = 0; g < 5; g++) acc[s][g] = 0.f;

    for (int k0 = 0; k0 < TWO_H; k0 += 32) {
#pragma unroll
        for (int i = 0; i < 4; i++) {
            int idx = tid + i * 256;
            int r = idx >> 5, c = idx & 31;
            Xs[r][c] = xin[(bt * 32 + r) * TWO_H + k0 + c];
        }
#pragma unroll
        for (int i = 0; i < 10; i++) {
            int idx = tid + i * 256;
            int kk = idx / 80, c = idx - kk * 80;
            int g = c >> 4, j = c & 15;
            Ws[c][kk] = W[(k0 + kk) * FIVE_H + g * HH + jt * 16 + j];
        }
        __syncthreads();
#pragma unroll
        for (int kk = 0; kk < 32; kk += 4) {
            float4 x0 = *reinterpret_cast<const float4*>(&Xs[bl][kk]);
            float4 x1 = *reinterpret_cast<const float4*>(&Xs[bl + 16][kk]);
#pragma unroll
            for (int g = 0; g < 5; g++) {
                float4 w = *reinterpret_cast<const float4*>(&Ws[g * 16 + jl][kk]);
                acc[0][g] += x0.x * w.x + x0.y * w.y + x0.z * w.z + x0.w * w.w;
                acc[1][g] += x1.x * w.x + x1.y * w.y + x1.z * w.z + x1.w * w.w;
            }
        }
        __syncthreads();
    }

    const int j = jt * 16 + jl;
    float bias[5];
#pragma unroll
    for (int g = 0; g < 5; g++) bias[g] = br[g * HH + j];

#pragma unroll
    for (int s = 0; s < 2; s++) {
        int b = bt * 32 + bl + s * 16;
        int mo = t * BB + b;
        int i1 = g_i1[mo], i2 = g_i2[mo], pos = g_pos[mo];
        int bi = g_bi[mo],  flg = g_flg[mo];

        float ai  = acc[s][0] + bias[0];
        float afl = acc[s][1] + bias[1];
        float afr = acc[s][2] + bias[2];
        float ao  = acc[s][3] + bias[3];
        float ag  = acc[s][4] + bias[4];

        float cl = g_stack_c[(b * SS + i2) * HH + j];
        float cr = g_stack_c[(b * SS + i1) * HH + j];
        float cred = sigf(afl) * cl + sigf(afr) * cr + sigf(ai) * tanhf(ag);
        float hred = sigf(ao) * tanhf(cred);

        float h, c;
        if (flg & 1) {          // SHIFT: take word buffer
            h = g_hbuf[(b * LL + bi) * HH + j];
            c = g_cbuf[(b * LL + bi) * HH + j];
        } else {
            h = hred; c = cred;
        }
        if (flg & 2) {
            g_stack_h[(b * SS + pos) * HH + j] = h;
            g_stack_c[(b * SS + pos) * HH + j] = c;
        }
        if (t + 1 < TT) {       // produce next step's gather (same-thread ordering)
            int mo2 = (t + 1) * BB + b;
            int i1n = g_i1[mo2], i2n = g_i2[mo2];
            float xl = (i2n == pos) ? h : g_stack_h[(b * SS + i2n) * HH + j];
            float xr = (i1n == pos) ? h : g_stack_h[(b * SS + i1n) * HH + j];
            xout[b * TWO_H + j] = xl;
            xout[b * TWO_H + HH + j] = xr;
        }
    }
}

// ------------------------- final readout ------------------------------------
__global__ void final_kernel(float* __restrict__ out)
{
    int idx = blockIdx.x * blockDim.x + threadIdx.x;   // < 128*512
    if (idx >= BB * HH) return;
    int b = idx >> 9;
    int j = idx & 511;
    out[idx] = g_stack_h[(b * SS + g_fin[b]) * HH + j];
}

// ------------------------- launch -------------------------------------------
extern "C" void kernel_launch(void* const* d_in, const int* in_sizes, int n_in,
                              void* d_out, int out_size)
{
    const float* sentence    = (const float*)d_in[0];
    const int*   transitions = (const int*)  d_in[1];
    const float* word_W      = (const float*)d_in[2];
    const float* word_b      = (const float*)d_in[3];
    const float* bn_gamma    = (const float*)d_in[4];
    const float* bn_beta     = (const float*)d_in[5];
    const float* reduce_W    = (const float*)d_in[6];
    const float* reduce_b    = (const float*)d_in[7];
    float* out = (float*)d_out;

    // Phase A: word projection + batchnorm
    word_gemm<<<dim3(TWO_H / 64, NLE / 64), 256>>>(sentence, word_W, word_b);
    zero_stats<<<4, 256>>>();
    bn_stats<<<dim3(4, 256), 256>>>();
    bn_finalize<<<4, 256>>>(bn_gamma, bn_beta);
    bn_apply<<<(NLE * TWO_H) / 256, 256>>>();

    // Pointer metadata (data-independent)
    meta_kernel<<<1, 128>>>(transitions);

    // Sequential scan
    for (int t = 0; t < TT; t++) {
        step_kernel<<<dim3(32, 4), 256>>>(t, reduce_W, reduce_b);
    }

    final_kernel<<<(BB * HH + 255) / 256, 256>>>(out);
}

// round 5
// speedup vs baseline: 1.3613x; 1.3613x over previous
#include <cuda_runtime.h>
#include <math.h>

typedef unsigned long long ull;

// ---------------------------------------------------------------------------
// SPINN TreeLSTM, level-scheduled tree evaluation + f32x2 packed FMA.
// B=128, L=128, E=512, H=512, T=255, internal nodes per row NN=127.
// ---------------------------------------------------------------------------

#define BB 128
#define LL 128
#define EE 512
#define HH 512
#define TT 255
#define NN 127
#define TWO_H 1024
#define FIVE_H 2560
#define NLE (BB*LL)
#define SMALL_MAX 32

// ------------------------- scratch (static device memory) ------------------
__device__ float g_tmp[NLE * TWO_H];
__device__ float g_hbuf[BB * LL * HH];
__device__ float g_cbuf[BB * LL * HH];
__device__ float g_node_h[BB * NN * HH];
__device__ float g_node_c[BB * NN * HH];
__device__ float g_part[SMALL_MAX * FIVE_H * 4];   // small-path split-K partials
__device__ float g_sum[TWO_H];
__device__ float g_sumsq[TWO_H];
__device__ float g_scale[TWO_H];
__device__ float g_shift[TWO_H];
__device__ int2  g_ch[BB * NN];          // child ids: <128 leaf(word), >=128 node
__device__ int   g_items[BB * NN];       // (b<<7)|n, bucketed by level
__device__ int   g_lv_start[132];
__device__ int   g_maxlvl;
__device__ int   g_fin[BB];              // root id per row
__device__ int            g_bar_count;
__device__ volatile int   g_bar_gen;

__device__ __forceinline__ float sigf(float x) { return 1.0f / (1.0f + expf(-x)); }

__device__ __forceinline__ ull ffma2(ull x, ull w, ull a) {
    asm("fma.rn.f32x2 %0, %1, %2, %0;" : "+l"(a) : "l"(x), "l"(w));
    return a;
}
__device__ __forceinline__ float2 upk(ull v) {
    float2 f; asm("mov.b64 {%0, %1}, %2;" : "=f"(f.x), "=f"(f.y) : "l"(v)); return f;
}

__device__ __forceinline__ const float* hsrc(int b, int id) {
    return (id < 128) ? (g_hbuf + (b * LL + id) * HH)
                      : (g_node_h + (b * NN + (id - 128)) * HH);
}
__device__ __forceinline__ const float* csrc(int b, int id) {
    return (id < 128) ? (g_cbuf + (b * LL + id) * HH)
                      : (g_node_c + (b * NN + (id - 128)) * HH);
}

// Sense-reversing grid barrier. Producer release: bar.sync (block-cumulative)
// + leader __threadfence before gen bump. Consumer acquire: __threadfence
// after the spin observes the new generation.
__device__ __forceinline__ void grid_barrier(int nblk) {
    __syncthreads();
    if (threadIdx.x == 0) {
        __threadfence();
        int gen = g_bar_gen;
        if (atomicAdd(&g_bar_count, 1) == nblk - 1) {
            g_bar_count = 0;
            __threadfence();
            g_bar_gen = gen + 1;
        } else {
            while (g_bar_gen == gen) { __nanosleep(64); }
        }
        __threadfence();   // acquire side
    }
    __syncthreads();
}

// ------------------------- phase A: word GEMM -------------------------------
__global__ __launch_bounds__(256) void word_gemm(
    const float* __restrict__ A, const float* __restrict__ W,
    const float* __restrict__ bias)
{
    __shared__ float As[64][33];
    __shared__ float Bs[32][64];
    const int tx = threadIdx.x & 15;
    const int ty = threadIdx.x >> 4;
    const int rowBase = blockIdx.y * 64;
    const int colBase = blockIdx.x * 64;

    float acc[4][4];
#pragma unroll
    for (int i = 0; i < 4; i++)
#pragma unroll
        for (int j = 0; j < 4; j++) acc[i][j] = 0.f;

    for (int k0 = 0; k0 < EE; k0 += 32) {
#pragma unroll
        for (int i = 0; i < 8; i++) {
            int idx = threadIdx.x + i * 256;
            int r = idx >> 5, c = idx & 31;
            As[r][c] = A[(rowBase + r) * EE + k0 + c];
        }
#pragma unroll
        for (int i = 0; i < 8; i++) {
            int idx = threadIdx.x + i * 256;
            int r = idx >> 6, c = idx & 63;
            Bs[r][c] = W[(k0 + r) * TWO_H + colBase + c];
        }
        __syncthreads();
#pragma unroll
        for (int kk = 0; kk < 32; kk++) {
            float a0 = As[ty * 4 + 0][kk];
            float a1 = As[ty * 4 + 1][kk];
            float a2 = As[ty * 4 + 2][kk];
            float a3 = As[ty * 4 + 3][kk];
            float4 b4 = *reinterpret_cast<const float4*>(&Bs[kk][tx * 4]);
            acc[0][0] += a0 * b4.x; acc[0][1] += a0 * b4.y; acc[0][2] += a0 * b4.z; acc[0][3] += a0 * b4.w;
            acc[1][0] += a1 * b4.x; acc[1][1] += a1 * b4.y; acc[1][2] += a1 * b4.z; acc[1][3] += a1 * b4.w;
            acc[2][0] += a2 * b4.x; acc[2][1] += a2 * b4.y; acc[2][2] += a2 * b4.z; acc[2][3] += a2 * b4.w;
            acc[3][0] += a3 * b4.x; acc[3][1] += a3 * b4.y; acc[3][2] += a3 * b4.z; acc[3][3] += a3 * b4.w;
        }
        __syncthreads();
    }
#pragma unroll
    for (int i = 0; i < 4; i++)
#pragma unroll
        for (int j = 0; j < 4; j++) {
            int col = colBase + tx * 4 + j;
            g_tmp[(rowBase + ty * 4 + i) * TWO_H + col] = acc[i][j] + bias[col];
        }
}

// ------------------------- phase A: BatchNorm -------------------------------
__global__ void zero_stats()
{
    int ch = blockIdx.x * blockDim.x + threadIdx.x;
    if (ch < TWO_H) { g_sum[ch] = 0.f; g_sumsq[ch] = 0.f; }
}

__global__ __launch_bounds__(256) void bn_stats()
{
    int ch = blockIdx.x * 256 + threadIdx.x;
    int rowBase = blockIdx.y * 64;
    float s = 0.f, q = 0.f;
#pragma unroll 4
    for (int r = 0; r < 64; r++) {
        float v = g_tmp[(rowBase + r) * TWO_H + ch];
        s += v; q += v * v;
    }
    atomicAdd(&g_sum[ch], s);
    atomicAdd(&g_sumsq[ch], q);
}

__global__ void bn_finalize(const float* __restrict__ gamma, const float* __restrict__ beta)
{
    int ch = blockIdx.x * blockDim.x + threadIdx.x;
    if (ch >= TWO_H) return;
    const float invN = 1.0f / (float)NLE;
    float mean = g_sum[ch] * invN;
    float var  = g_sumsq[ch] * invN - mean * mean;
    float sc   = gamma[ch] * rsqrtf(var + 1e-5f);
    g_scale[ch] = sc;
    g_shift[ch] = beta[ch] - mean * sc;
}

__global__ __launch_bounds__(256) void bn_apply()
{
    int idx = blockIdx.x * 256 + threadIdx.x;
    int row = idx >> 10;
    int ch  = idx & 1023;
    float v = g_tmp[idx] * g_scale[ch] + g_shift[ch];
    if (ch < HH) g_hbuf[row * HH + ch] = v;
    else         g_cbuf[row * HH + (ch - HH)] = v;
}

// ------------------------- metadata: tree + level buckets -------------------
__global__ void meta_kernel(const int* __restrict__ trans)
{
    __shared__ int cnt[132];
    __shared__ int cur[132];
    __shared__ int smax;
    int b = threadIdx.x;
    for (int i = b; i < 132; i += 128) cnt[i] = 0;
    if (b == 0) smax = 0;
    __syncthreads();

    int sid[130];
    int slv[130];
    int nlv[NN];
    int ptr = 0, bp = 0, n = 0;
    for (int t = 0; t < TT; t++) {
        int act = trans[b * TT + t];
        if (act == 2) {                       // SHIFT
            sid[ptr] = bp; slv[ptr] = 0; ptr++; bp++;
        } else if (act == 3) {                // REDUCE
            int lv = max(slv[ptr - 2], slv[ptr - 1]) + 1;
            g_ch[b * NN + n] = make_int2(sid[ptr - 2], sid[ptr - 1]);
            nlv[n] = lv;
            sid[ptr - 2] = 128 + n; slv[ptr - 2] = lv;
            ptr--; n++;
        }
    }
    g_fin[b] = sid[0];                        // root (internal, >=128)

    int mymax = 0;
    for (int i = 0; i < n; i++) {
        atomicAdd(&cnt[nlv[i]], 1);
        mymax = max(mymax, nlv[i]);
    }
    atomicMax(&smax, mymax);
    __syncthreads();
    if (b == 0) {
        int a = 0;
        for (int lv = 0; lv <= 130; lv++) {
            cur[lv] = a;
            g_lv_start[lv] = a;
            a += cnt[lv];
        }
        g_lv_start[131] = a;
        g_maxlvl = smax;
    }
    __syncthreads();
    for (int i = 0; i < n; i++) {
        int idx = atomicAdd(&cur[nlv[i]], 1);
        g_items[idx] = (b << 7) | i;
    }
}

// ------------------------- persistent level-scan kernel ---------------------
// Big path tile: 64 nodes x (32 cols x 5 gates), K=1024 in 32-chunks,
// f32x2 packed over adjacent columns; register-prefetch software pipeline.
__global__ __launch_bounds__(256) void scan_kernel(
    const float* __restrict__ W, const float* __restrict__ rb, int nblk)
{
    __shared__ __align__(16) float  Ws[32 * 5 * 32];   // [k][gate][c] 20KB
    __shared__ __align__(16) float2 Xs[64 * 32];       // [node][k] dup 16KB
    __shared__ const float* sm_hl[64];
    __shared__ const float* sm_hr[64];
    __shared__ const float* sm_cl[64];
    __shared__ const float* sm_cr[64];
    __shared__ int sm_out[64];

    const int tid = threadIdx.x;
    const int maxlvl = g_maxlvl;

    for (int lv = 1; lv <= maxlvl; lv++) {
        const int start = g_lv_start[lv];
        const int M = g_lv_start[lv + 1] - start;

        if (M > SMALL_MAX) {
            const int mtiles = (M + 63) >> 6;
            const int tiles = mtiles * 16;
            for (int tile = blockIdx.x; tile < tiles; tile += nblk) {
                const int jt = tile & 15;          // 16 col-tiles of 32
                const int mt = tile >> 4;

                if (tid < 64) {
                    int gi = start + mt * 64 + tid;
                    bool valid = gi < start + M;
                    int item = g_items[valid ? gi : start];
                    int b = item >> 7, n = item & 127;
                    int2 ch = g_ch[b * NN + n];
                    sm_hl[tid] = hsrc(b, ch.x);
                    sm_hr[tid] = hsrc(b, ch.y);
                    sm_cl[tid] = csrc(b, ch.x);
                    sm_cr[tid] = csrc(b, ch.y);
                    sm_out[tid] = valid ? (b * NN + n) : -1;
                }
                __syncthreads();

                ull acc[2][2][5];
#pragma unroll
                for (int s = 0; s < 2; s++)
#pragma unroll
                    for (int p = 0; p < 2; p++)
#pragma unroll
                        for (int g = 0; g < 5; g++) acc[s][p][g] = 0ull;

                float  xr[8];
                float4 wr[5];
                // prefetch chunk 0
                {
                    const int kc0 = 0;
#pragma unroll
                    for (int i = 0; i < 8; i++) {
                        int flat = tid + i * 256;
                        int r = flat >> 5, k = flat & 31;
                        xr[i] = sm_hl[r][kc0 + k];
                    }
#pragma unroll
                    for (int i = 0; i < 5; i++) {
                        int f4 = tid + i * 256;
                        int c4 = f4 & 7, g = (f4 >> 3) % 5, k = f4 / 40;
                        wr[i] = *(const float4*)(W + (kc0 + k) * FIVE_H + g * HH + jt * 32 + c4 * 4);
                    }
                }

                const int ng = tid >> 3, jg = tid & 7;
                const ull* xb0 = (const ull*)Xs + (ng * 2) * 32;
                const ull* xb1 = xb0 + 32;

                for (int chk = 0; chk < 32; chk++) {
                    // stage regs -> smem
#pragma unroll
                    for (int i = 0; i < 8; i++)
                        Xs[tid + i * 256] = make_float2(xr[i], xr[i]);
#pragma unroll
                    for (int i = 0; i < 5; i++)
                        *(float4*)&Ws[(tid + i * 256) * 4] = wr[i];
                    __syncthreads();

                    // prefetch next chunk (overlaps with compute below)
                    if (chk < 31) {
                        const int kc0 = (chk + 1) * 32;
                        const bool left = kc0 < HH;
                        const int koff = left ? kc0 : (kc0 - HH);
#pragma unroll
                        for (int i = 0; i < 8; i++) {
                            int flat = tid + i * 256;
                            int r = flat >> 5, k = flat & 31;
                            const float* base = (left ? sm_hl[r] : sm_hr[r]) + koff;
                            xr[i] = base[k];
                        }
#pragma unroll
                        for (int i = 0; i < 5; i++) {
                            int f4 = tid + i * 256;
                            int c4 = f4 & 7, g = (f4 >> 3) % 5, k = f4 / 40;
                            wr[i] = *(const float4*)(W + (kc0 + k) * FIVE_H + g * HH + jt * 32 + c4 * 4);
                        }
                    }

#pragma unroll 8
                    for (int k = 0; k < 32; k++) {
                        ull x0 = xb0[k];
                        ull x1 = xb1[k];
#pragma unroll
                        for (int g = 0; g < 5; g++) {
                            ulonglong2 w = *(const ulonglong2*)&Ws[(k * 5 + g) * 32 + jg * 4];
                            acc[0][0][g] = ffma2(x0, w.x, acc[0][0][g]);
                            acc[0][1][g] = ffma2(x0, w.y, acc[0][1][g]);
                            acc[1][0][g] = ffma2(x1, w.x, acc[1][0][g]);
                            acc[1][1][g] = ffma2(x1, w.y, acc[1][1][g]);
                        }
                    }
                    __syncthreads();
                }

                // epilogue: all 5 gates in-registers
#pragma unroll
                for (int s = 0; s < 2; s++) {
                    int r = ng * 2 + s;
                    int o = sm_out[r];
                    if (o < 0) continue;
                    const float* clp = sm_cl[r];
                    const float* crp = sm_cr[r];
#pragma unroll
                    for (int p = 0; p < 2; p++) {
                        int col = jt * 32 + jg * 4 + p * 2;
                        float2 vi  = upk(acc[s][p][0]);
                        float2 vfl = upk(acc[s][p][1]);
                        float2 vfr = upk(acc[s][p][2]);
                        float2 vo  = upk(acc[s][p][3]);
                        float2 vg  = upk(acc[s][p][4]);
                        float2 bi  = *(const float2*)(rb + 0 * HH + col);
                        float2 bfl = *(const float2*)(rb + 1 * HH + col);
                        float2 bfr = *(const float2*)(rb + 2 * HH + col);
                        float2 bo  = *(const float2*)(rb + 3 * HH + col);
                        float2 bg  = *(const float2*)(rb + 4 * HH + col);
                        float2 cl = *(const float2*)(clp + col);
                        float2 cr = *(const float2*)(crp + col);
                        float2 c, h;
                        c.x = sigf(vfl.x + bfl.x) * cl.x + sigf(vfr.x + bfr.x) * cr.x
                            + sigf(vi.x + bi.x) * tanhf(vg.x + bg.x);
                        c.y = sigf(vfl.y + bfl.y) * cl.y + sigf(vfr.y + bfr.y) * cr.y
                            + sigf(vi.y + bi.y) * tanhf(vg.y + bg.y);
                        h.x = sigf(vo.x + bo.x) * tanhf(c.x);
                        h.y = sigf(vo.y + bo.y) * tanhf(c.y);
                        *(float2*)&g_node_h[o * HH + col] = h;
                        *(float2*)&g_node_c[o * HH + col] = c;
                    }
                }
                __syncthreads();
            }
            grid_barrier(nblk);
        } else {
            // ---------------- small path: deterministic split-K --------------
            int total1 = 4 * M * FIVE_H;
            for (int f = blockIdx.x * 256 + tid; f < total1; f += nblk * 256) {
                int col = f % FIVE_H;
                int rest = f / FIVE_H;
                int i = rest % M, ks = rest / M;
                int item = g_items[start + i];
                int b = item >> 7, n = item & 127;
                int2 ch = g_ch[b * NN + n];
                const float* xp = (ks < 2 ? hsrc(b, ch.x) : hsrc(b, ch.y)) + (ks & 1) * 256;
                const float* wp = W + (ks * 256) * FIVE_H + col;
                float s = 0.f;
#pragma unroll 8
                for (int k = 0; k < 256; k++) s += xp[k] * wp[k * FIVE_H];
                g_part[(i * FIVE_H + col) * 4 + ks] = s;
            }
            grid_barrier(nblk);
            int total2 = M * HH;
            for (int f = blockIdx.x * 256 + tid; f < total2; f += nblk * 256) {
                int j = f & 511, i = f >> 9;
                int item = g_items[start + i];
                int b = item >> 7, n = item & 127;
                int2 ch = g_ch[b * NN + n];
                float ga[5];
#pragma unroll
                for (int g = 0; g < 5; g++) {
                    float4 p4 = *(const float4*)&g_part[(i * FIVE_H + g * HH + j) * 4];
                    ga[g] = ((p4.x + p4.y) + (p4.z + p4.w)) + rb[g * HH + j];
                }
                float cl = csrc(b, ch.x)[j];
                float cr = csrc(b, ch.y)[j];
                float c = sigf(ga[1]) * cl + sigf(ga[2]) * cr + sigf(ga[0]) * tanhf(ga[4]);
                float h = sigf(ga[3]) * tanhf(c);
                int o = b * NN + n;
                g_node_h[o * HH + j] = h;
                g_node_c[o * HH + j] = c;
            }
            grid_barrier(nblk);
        }
    }
}

// ------------------------- final readout ------------------------------------
__global__ void final_kernel(float* __restrict__ out)
{
    int idx = blockIdx.x * blockDim.x + threadIdx.x;
    if (idx >= BB * HH) return;
    int b = idx >> 9;
    int j = idx & 511;
    int root = g_fin[b] - 128;              // root is always internal
    out[idx] = g_node_h[(b * NN + root) * HH + j];
}

// ------------------------- launch -------------------------------------------
extern "C" void kernel_launch(void* const* d_in, const int* in_sizes, int n_in,
                              void* d_out, int out_size)
{
    const float* sentence    = (const float*)d_in[0];
    const int*   transitions = (const int*)  d_in[1];
    const float* word_W      = (const float*)d_in[2];
    const float* word_b      = (const float*)d_in[3];
    const float* bn_gamma    = (const float*)d_in[4];
    const float* bn_beta     = (const float*)d_in[5];
    const float* reduce_W    = (const float*)d_in[6];
    const float* reduce_b    = (const float*)d_in[7];
    float* out = (float*)d_out;

    int dev = 0, nsm = 148;
    cudaGetDevice(&dev);
    cudaDeviceGetAttribute(&nsm, cudaDevAttrMultiProcessorCount, dev);

    word_gemm<<<dim3(TWO_H / 64, NLE / 64), 256>>>(sentence, word_W, word_b);
    zero_stats<<<4, 256>>>();
    bn_stats<<<dim3(4, 256), 256>>>();
    bn_finalize<<<4, 256>>>(bn_gamma, bn_beta);
    bn_apply<<<(NLE * TWO_H) / 256, 256>>>();

    meta_kernel<<<1, 128>>>(transitions);

    scan_kernel<<<nsm, 256>>>(reduce_W, reduce_b, nsm);

    final_kernel<<<(BB * HH + 255) / 256, 256>>>(out);
}

// round 6
// speedup vs baseline: 2.0850x; 1.5316x over previous
#include <cuda_runtime.h>
#include <math.h>

typedef unsigned long long ull;

// ---------------------------------------------------------------------------
// SPINN TreeLSTM: level-scheduled tree evaluation, uniform split-K tiles,
// f32x2 packed FMA. B=128, L=128, E=512, H=512, nodes/row NN=127.
// ---------------------------------------------------------------------------

#define BB 128
#define LL 128
#define EE 512
#define HH 512
#define TT 255
#define NN 127
#define TWO_H 1024
#define FIVE_H 2560
#define NLE (BB*LL)
#define PS 8                     // partial stride (max splits)

// ------------------------- scratch (static device memory) ------------------
__device__ float g_tmp[NLE * TWO_H];
__device__ float g_hbuf[BB * LL * HH];
__device__ float g_cbuf[BB * LL * HH];
__device__ float g_node_h[BB * NN * HH];
__device__ float g_node_c[BB * NN * HH];
__device__ float g_part[256 * FIVE_H * PS];      // split-K partials (21MB)
__device__ float g_sum[TWO_H];
__device__ float g_sumsq[TWO_H];
__device__ float g_scale[TWO_H];
__device__ float g_shift[TWO_H];
__device__ int2  g_ch[BB * NN];          // child ids: <128 leaf(word), >=128 node
__device__ int   g_items[BB * NN];       // (b<<7)|n, bucketed by level
__device__ int   g_lv_start[132];
__device__ int   g_maxlvl;
__device__ int   g_fin[BB];              // root id per row
__device__ int            g_bar_count;
__device__ volatile int   g_bar_gen;

__device__ __forceinline__ float sigf(float x) { return 1.0f / (1.0f + expf(-x)); }

__device__ __forceinline__ ull ffma2(ull x, ull w, ull a) {
    asm("fma.rn.f32x2 %0, %1, %2, %0;" : "+l"(a) : "l"(x), "l"(w));
    return a;
}
__device__ __forceinline__ float2 upk(ull v) {
    float2 f; asm("mov.b64 {%0, %1}, %2;" : "=f"(f.x), "=f"(f.y) : "l"(v)); return f;
}

__device__ __forceinline__ const float* hsrc(int b, int id) {
    return (id < 128) ? (g_hbuf + (b * LL + id) * HH)
                      : (g_node_h + (b * NN + (id - 128)) * HH);
}
__device__ __forceinline__ const float* csrc(int b, int id) {
    return (id < 128) ? (g_cbuf + (b * LL + id) * HH)
                      : (g_node_c + (b * NN + (id - 128)) * HH);
}

// Sense-reversing grid barrier (release: bar.sync + fence; acquire: fence).
__device__ __forceinline__ void grid_barrier(int nblk) {
    __syncthreads();
    if (threadIdx.x == 0) {
        __threadfence();
        int gen = g_bar_gen;
        if (atomicAdd(&g_bar_count, 1) == nblk - 1) {
            g_bar_count = 0;
            __threadfence();
            g_bar_gen = gen + 1;
        } else {
            while (g_bar_gen == gen) { __nanosleep(32); }
        }
        __threadfence();
    }
    __syncthreads();
}

// ------------------------- phase A: word GEMM -------------------------------
__global__ __launch_bounds__(256) void word_gemm(
    const float* __restrict__ A, const float* __restrict__ W,
    const float* __restrict__ bias)
{
    __shared__ float As[64][33];
    __shared__ float Bs[32][64];
    const int tx = threadIdx.x & 15;
    const int ty = threadIdx.x >> 4;
    const int rowBase = blockIdx.y * 64;
    const int colBase = blockIdx.x * 64;

    float acc[4][4];
#pragma unroll
    for (int i = 0; i < 4; i++)
#pragma unroll
        for (int j = 0; j < 4; j++) acc[i][j] = 0.f;

    for (int k0 = 0; k0 < EE; k0 += 32) {
#pragma unroll
        for (int i = 0; i < 8; i++) {
            int idx = threadIdx.x + i * 256;
            int r = idx >> 5, c = idx & 31;
            As[r][c] = A[(rowBase + r) * EE + k0 + c];
        }
#pragma unroll
        for (int i = 0; i < 8; i++) {
            int idx = threadIdx.x + i * 256;
            int r = idx >> 6, c = idx & 63;
            Bs[r][c] = W[(k0 + r) * TWO_H + colBase + c];
        }
        __syncthreads();
#pragma unroll
        for (int kk = 0; kk < 32; kk++) {
            float a0 = As[ty * 4 + 0][kk];
            float a1 = As[ty * 4 + 1][kk];
            float a2 = As[ty * 4 + 2][kk];
            float a3 = As[ty * 4 + 3][kk];
            float4 b4 = *reinterpret_cast<const float4*>(&Bs[kk][tx * 4]);
            acc[0][0] += a0 * b4.x; acc[0][1] += a0 * b4.y; acc[0][2] += a0 * b4.z; acc[0][3] += a0 * b4.w;
            acc[1][0] += a1 * b4.x; acc[1][1] += a1 * b4.y; acc[1][2] += a1 * b4.z; acc[1][3] += a1 * b4.w;
            acc[2][0] += a2 * b4.x; acc[2][1] += a2 * b4.y; acc[2][2] += a2 * b4.z; acc[2][3] += a2 * b4.w;
            acc[3][0] += a3 * b4.x; acc[3][1] += a3 * b4.y; acc[3][2] += a3 * b4.z; acc[3][3] += a3 * b4.w;
        }
        __syncthreads();
    }
#pragma unroll
    for (int i = 0; i < 4; i++)
#pragma unroll
        for (int j = 0; j < 4; j++) {
            int col = colBase + tx * 4 + j;
            g_tmp[(rowBase + ty * 4 + i) * TWO_H + col] = acc[i][j] + bias[col];
        }
}

// ------------------------- phase A: BatchNorm -------------------------------
__global__ void zero_stats()
{
    int ch = blockIdx.x * blockDim.x + threadIdx.x;
    if (ch < TWO_H) { g_sum[ch] = 0.f; g_sumsq[ch] = 0.f; }
}

__global__ __launch_bounds__(256) void bn_stats()
{
    int ch = blockIdx.x * 256 + threadIdx.x;
    int rowBase = blockIdx.y * 64;
    float s = 0.f, q = 0.f;
#pragma unroll 4
    for (int r = 0; r < 64; r++) {
        float v = g_tmp[(rowBase + r) * TWO_H + ch];
        s += v; q += v * v;
    }
    atomicAdd(&g_sum[ch], s);
    atomicAdd(&g_sumsq[ch], q);
}

__global__ void bn_finalize(const float* __restrict__ gamma, const float* __restrict__ beta)
{
    int ch = blockIdx.x * blockDim.x + threadIdx.x;
    if (ch >= TWO_H) return;
    const float invN = 1.0f / (float)NLE;
    float mean = g_sum[ch] * invN;
    float var  = g_sumsq[ch] * invN - mean * mean;
    float sc   = gamma[ch] * rsqrtf(var + 1e-5f);
    g_scale[ch] = sc;
    g_shift[ch] = beta[ch] - mean * sc;
}

__global__ __launch_bounds__(256) void bn_apply()
{
    int idx = blockIdx.x * 256 + threadIdx.x;
    int row = idx >> 10;
    int ch  = idx & 1023;
    float v = g_tmp[idx] * g_scale[ch] + g_shift[ch];
    if (ch < HH) g_hbuf[row * HH + ch] = v;
    else         g_cbuf[row * HH + (ch - HH)] = v;
}

// ------------------------- metadata: tree + level buckets -------------------
__global__ void meta_kernel(const int* __restrict__ trans)
{
    __shared__ int cnt[132];
    __shared__ int cur[132];
    __shared__ int smax;
    int b = threadIdx.x;
    for (int i = b; i < 132; i += 128) cnt[i] = 0;
    if (b == 0) smax = 0;
    __syncthreads();

    int sid[130];
    int slv[130];
    int nlv[NN];
    int ptr = 0, bp = 0, n = 0;
    for (int t = 0; t < TT; t++) {
        int act = trans[b * TT + t];
        if (act == 2) {                       // SHIFT
            sid[ptr] = bp; slv[ptr] = 0; ptr++; bp++;
        } else if (act == 3) {                // REDUCE
            int lv = max(slv[ptr - 2], slv[ptr - 1]) + 1;
            g_ch[b * NN + n] = make_int2(sid[ptr - 2], sid[ptr - 1]);
            nlv[n] = lv;
            sid[ptr - 2] = 128 + n; slv[ptr - 2] = lv;
            ptr--; n++;
        }
    }
    g_fin[b] = sid[0];

    int mymax = 0;
    for (int i = 0; i < n; i++) {
        atomicAdd(&cnt[nlv[i]], 1);
        mymax = max(mymax, nlv[i]);
    }
    atomicMax(&smax, mymax);
    __syncthreads();
    if (b == 0) {
        int a = 0;
        for (int lv = 0; lv <= 130; lv++) {
            cur[lv] = a;
            g_lv_start[lv] = a;
            a += cnt[lv];
        }
        g_lv_start[131] = a;
        g_maxlvl = smax;
    }
    __syncthreads();
    for (int i = 0; i < n; i++) {
        int idx = atomicAdd(&cur[nlv[i]], 1);
        g_items[idx] = (b << 7) | i;
    }
}

// ------------------------- persistent level-scan kernel ---------------------
// Uniform tile: 64 nodes x (32 cols x 5 gates). Per level, split factor
// sv in {1,2,4,8} chosen so tiles*sv fills the grid; each unit does 32/sv
// K-chunks. sv==1: fused in-register epilogue. sv>1: partials + reduce pass.
__global__ __launch_bounds__(256) void scan_kernel(
    const float* __restrict__ W, const float* __restrict__ rb, int nblk)
{
    __shared__ __align__(16) float  Ws[32 * 5 * 32];   // [k][gate][c] 20KB
    __shared__ __align__(16) float2 Xs[64 * 32];       // [node][k] dup 16KB
    __shared__ const float* sm_hl[64];
    __shared__ const float* sm_hr[64];
    __shared__ const float* sm_cl[64];
    __shared__ const float* sm_cr[64];
    __shared__ int sm_out[64];   // node slot (b*NN+n) or -1
    __shared__ int sm_idx[64];   // level-local index or -1

    const int tid = threadIdx.x;
    const int maxlvl = g_maxlvl;

    for (int lv = 1; lv <= maxlvl; lv++) {
        const int start = g_lv_start[lv];
        const int M = g_lv_start[lv + 1] - start;
        if (M <= 0) { grid_barrier(nblk); continue; }

        const int mtiles = (M + 63) >> 6;
        const int base_tiles = mtiles * 16;
        int sv = 1;
        while (sv < PS && base_tiles * (sv << 1) <= nblk) sv <<= 1;
        const int cpu = 32 / sv;                  // chunks per unit
        const int units = base_tiles * sv;

        for (int u = blockIdx.x; u < units; u += nblk) {
            const int tile = u % base_tiles;
            const int split = u / base_tiles;
            const int jt = tile & 15;
            const int mt = tile >> 4;
            const int c0 = split * cpu, c1 = c0 + cpu;

            if (tid < 64) {
                int gi = start + mt * 64 + tid;
                bool valid = gi < start + M;
                int item = g_items[valid ? gi : start];
                int b = item >> 7, n = item & 127;
                int2 ch = g_ch[b * NN + n];
                sm_hl[tid] = hsrc(b, ch.x);
                sm_hr[tid] = hsrc(b, ch.y);
                sm_cl[tid] = csrc(b, ch.x);
                sm_cr[tid] = csrc(b, ch.y);
                sm_out[tid] = valid ? (b * NN + n) : -1;
                sm_idx[tid] = valid ? (mt * 64 + tid) : -1;
            }
            __syncthreads();

            ull acc[2][2][5];
#pragma unroll
            for (int s = 0; s < 2; s++)
#pragma unroll
                for (int p = 0; p < 2; p++)
#pragma unroll
                    for (int g = 0; g < 5; g++) acc[s][p][g] = 0ull;

            float  xr[8];
            float4 wr[5];
            // prefetch first chunk
            {
                const int kc0 = c0 * 32;
                const bool left = kc0 < HH;
                const int koff = left ? kc0 : (kc0 - HH);
#pragma unroll
                for (int i = 0; i < 8; i++) {
                    int flat = tid + i * 256;
                    int r = flat >> 5, k = flat & 31;
                    xr[i] = ((left ? sm_hl[r] : sm_hr[r]) + koff)[k];
                }
#pragma unroll
                for (int i = 0; i < 5; i++) {
                    int f4 = tid + i * 256;
                    int c4 = f4 & 7, g = (f4 >> 3) % 5, k = f4 / 40;
                    wr[i] = *(const float4*)(W + (kc0 + k) * FIVE_H + g * HH + jt * 32 + c4 * 4);
                }
            }

            const int ng = tid >> 3, jg = tid & 7;
            const ull* xb0 = (const ull*)Xs + (ng * 2) * 32;
            const ull* xb1 = xb0 + 32;

            for (int chk = c0; chk < c1; chk++) {
#pragma unroll
                for (int i = 0; i < 8; i++)
                    Xs[tid + i * 256] = make_float2(xr[i], xr[i]);
#pragma unroll
                for (int i = 0; i < 5; i++)
                    *(float4*)&Ws[(tid + i * 256) * 4] = wr[i];
                __syncthreads();

                if (chk + 1 < c1) {
                    const int kc0 = (chk + 1) * 32;
                    const bool left = kc0 < HH;
                    const int koff = left ? kc0 : (kc0 - HH);
#pragma unroll
                    for (int i = 0; i < 8; i++) {
                        int flat = tid + i * 256;
                        int r = flat >> 5, k = flat & 31;
                        xr[i] = ((left ? sm_hl[r] : sm_hr[r]) + koff)[k];
                    }
#pragma unroll
                    for (int i = 0; i < 5; i++) {
                        int f4 = tid + i * 256;
                        int c4 = f4 & 7, g = (f4 >> 3) % 5, k = f4 / 40;
                        wr[i] = *(const float4*)(W + (kc0 + k) * FIVE_H + g * HH + jt * 32 + c4 * 4);
                    }
                }

#pragma unroll 8
                for (int k = 0; k < 32; k++) {
                    ull x0 = xb0[k];
                    ull x1 = xb1[k];
#pragma unroll
                    for (int g = 0; g < 5; g++) {
                        ulonglong2 w = *(const ulonglong2*)&Ws[(k * 5 + g) * 32 + jg * 4];
                        acc[0][0][g] = ffma2(x0, w.x, acc[0][0][g]);
                        acc[0][1][g] = ffma2(x0, w.y, acc[0][1][g]);
                        acc[1][0][g] = ffma2(x1, w.x, acc[1][0][g]);
                        acc[1][1][g] = ffma2(x1, w.y, acc[1][1][g]);
                    }
                }
                __syncthreads();
            }

            if (sv == 1) {
                // fused epilogue, all 5 gates in registers
#pragma unroll
                for (int s = 0; s < 2; s++) {
                    int r = ng * 2 + s;
                    int o = sm_out[r];
                    if (o < 0) continue;
                    const float* clp = sm_cl[r];
                    const float* crp = sm_cr[r];
#pragma unroll
                    for (int p = 0; p < 2; p++) {
                        int col = jt * 32 + jg * 4 + p * 2;
                        float2 vi  = upk(acc[s][p][0]);
                        float2 vfl = upk(acc[s][p][1]);
                        float2 vfr = upk(acc[s][p][2]);
                        float2 vo  = upk(acc[s][p][3]);
                        float2 vg  = upk(acc[s][p][4]);
                        float2 bi  = *(const float2*)(rb + 0 * HH + col);
                        float2 bfl = *(const float2*)(rb + 1 * HH + col);
                        float2 bfr = *(const float2*)(rb + 2 * HH + col);
                        float2 bo  = *(const float2*)(rb + 3 * HH + col);
                        float2 bg  = *(const float2*)(rb + 4 * HH + col);
                        float2 cl = *(const float2*)(clp + col);
                        float2 cr = *(const float2*)(crp + col);
                        float2 c, h;
                        c.x = sigf(vfl.x + bfl.x) * cl.x + sigf(vfr.x + bfr.x) * cr.x
                            + sigf(vi.x + bi.x) * tanhf(vg.x + bg.x);
                        c.y = sigf(vfl.y + bfl.y) * cl.y + sigf(vfr.y + bfr.y) * cr.y
                            + sigf(vi.y + bi.y) * tanhf(vg.y + bg.y);
                        h.x = sigf(vo.x + bo.x) * tanhf(c.x);
                        h.y = sigf(vo.y + bo.y) * tanhf(c.y);
                        *(float2*)&g_node_h[o * HH + col] = h;
                        *(float2*)&g_node_c[o * HH + col] = c;
                    }
                }
            } else {
                // write split-K partials
#pragma unroll
                for (int s = 0; s < 2; s++) {
                    int r = ng * 2 + s;
                    int idx = sm_idx[r];
                    if (idx < 0) continue;
#pragma unroll
                    for (int p = 0; p < 2; p++) {
                        int col = jt * 32 + jg * 4 + p * 2;
#pragma unroll
                        for (int g = 0; g < 5; g++) {
                            float2 v = upk(acc[s][p][g]);
                            int base = (idx * FIVE_H + g * HH + col) * PS + split;
                            g_part[base] = v.x;
                            g_part[base + PS] = v.y;
                        }
                    }
                }
            }
            __syncthreads();
        }
        grid_barrier(nblk);

        if (sv > 1) {
            // reduce partials (fixed order) + LSTM epilogue
            int total2 = M * HH;
            for (int f = blockIdx.x * 256 + tid; f < total2; f += nblk * 256) {
                int j = f & 511, i = f >> 9;
                int item = g_items[start + i];
                int b = item >> 7, n = item & 127;
                int2 ch = g_ch[b * NN + n];
                float ga[5];
#pragma unroll
                for (int g = 0; g < 5; g++) {
                    int base = (i * FIVE_H + g * HH + j) * PS;
                    float s = 0.f;
                    for (int t = 0; t < sv; t++) s += g_part[base + t];
                    ga[g] = s + rb[g * HH + j];
                }
                float cl = csrc(b, ch.x)[j];
                float cr = csrc(b, ch.y)[j];
                float c = sigf(ga[1]) * cl + sigf(ga[2]) * cr + sigf(ga[0]) * tanhf(ga[4]);
                float h = sigf(ga[3]) * tanhf(c);
                int o = b * NN + n;
                g_node_h[o * HH + j] = h;
                g_node_c[o * HH + j] = c;
            }
            grid_barrier(nblk);
        }
    }
}

// ------------------------- final readout ------------------------------------
__global__ void final_kernel(float* __restrict__ out)
{
    int idx = blockIdx.x * blockDim.x + threadIdx.x;
    if (idx >= BB * HH) return;
    int b = idx >> 9;
    int j = idx & 511;
    int root = g_fin[b] - 128;
    out[idx] = g_node_h[(b * NN + root) * HH + j];
}

// ------------------------- launch -------------------------------------------
extern "C" void kernel_launch(void* const* d_in, const int* in_sizes, int n_in,
                              void* d_out, int out_size)
{
    const float* sentence    = (const float*)d_in[0];
    const int*   transitions = (const int*)  d_in[1];
    const float* word_W      = (const float*)d_in[2];
    const float* word_b      = (const float*)d_in[3];
    const float* bn_gamma    = (const float*)d_in[4];
    const float* bn_beta     = (const float*)d_in[5];
    const float* reduce_W    = (const float*)d_in[6];
    const float* reduce_b    = (const float*)d_in[7];
    float* out = (float*)d_out;

    int dev = 0, nsm = 148;
    cudaGetDevice(&dev);
    cudaDeviceGetAttribute(&nsm, cudaDevAttrMultiProcessorCount, dev);

    word_gemm<<<dim3(TWO_H / 64, NLE / 64), 256>>>(sentence, word_W, word_b);
    zero_stats<<<4, 256>>>();
    bn_stats<<<dim3(4, 256), 256>>>();
    bn_finalize<<<4, 256>>>(bn_gamma, bn_beta);
    bn_apply<<<(NLE * TWO_H) / 256, 256>>>();

    meta_kernel<<<1, 128>>>(transitions);

    scan_kernel<<<nsm, 256>>>(reduce_W, reduce_b, nsm);

    final_kernel<<<(BB * HH + 255) / 256, 256>>>(out);
}

// round 7
// speedup vs baseline: 2.8458x; 1.3649x over previous
#include <cuda_runtime.h>
#include <math.h>

typedef unsigned long long ull;

// ---------------------------------------------------------------------------
// SPINN TreeLSTM: level-scheduled tree evaluation, uniform split-K tiles,
// f32x2 packed FMA, conflict-free smem layouts.
// B=128, L=128, E=512, H=512, nodes/row NN=127.
// ---------------------------------------------------------------------------

#define BB 128
#define LL 128
#define EE 512
#define HH 512
#define TT 255
#define NN 127
#define TWO_H 1024
#define FIVE_H 2560
#define NLE (BB*LL)
#define PS 8                     // partial stride (max splits)

// ------------------------- scratch (static device memory) ------------------
__device__ float g_tmp[NLE * TWO_H];
__device__ float g_hbuf[BB * LL * HH];
__device__ float g_cbuf[BB * LL * HH];
__device__ float g_node_h[BB * NN * HH];
__device__ float g_node_c[BB * NN * HH];
__device__ float g_part[512 * FIVE_H * PS];      // split-K partials (42MB)
__device__ float g_sum[TWO_H];
__device__ float g_sumsq[TWO_H];
__device__ float g_scale[TWO_H];
__device__ float g_shift[TWO_H];
__device__ int2  g_ch[BB * NN];          // child ids: <128 leaf(word), >=128 node
__device__ int   g_items[BB * NN];       // (b<<7)|n, bucketed by level
__device__ int   g_lv_start[132];
__device__ int   g_maxlvl;
__device__ int   g_fin[BB];              // root id per row
__device__ int            g_bar_count;
__device__ volatile int   g_bar_gen;

__device__ __forceinline__ float sigf(float x) { return 1.0f / (1.0f + expf(-x)); }

__device__ __forceinline__ ull ffma2(ull x, ull w, ull a) {
    asm("fma.rn.f32x2 %0, %1, %2, %0;" : "+l"(a) : "l"(x), "l"(w));
    return a;
}
__device__ __forceinline__ ull pk2(float v) {
    ull r; asm("mov.b64 %0, {%1, %2};" : "=l"(r) : "f"(v), "f"(v)); return r;
}
__device__ __forceinline__ float2 upk(ull v) {
    float2 f; asm("mov.b64 {%0, %1}, %2;" : "=f"(f.x), "=f"(f.y) : "l"(v)); return f;
}

__device__ __forceinline__ const float* hsrc(int b, int id) {
    return (id < 128) ? (g_hbuf + (b * LL + id) * HH)
                      : (g_node_h + (b * NN + (id - 128)) * HH);
}
__device__ __forceinline__ const float* csrc(int b, int id) {
    return (id < 128) ? (g_cbuf + (b * LL + id) * HH)
                      : (g_node_c + (b * NN + (id - 128)) * HH);
}

// Sense-reversing grid barrier (release: bar.sync + fence; acquire: fence).
__device__ __forceinline__ void grid_barrier(int nblk) {
    __syncthreads();
    if (threadIdx.x == 0) {
        __threadfence();
        int gen = g_bar_gen;
        if (atomicAdd(&g_bar_count, 1) == nblk - 1) {
            g_bar_count = 0;
            __threadfence();
            g_bar_gen = gen + 1;
        } else {
            while (g_bar_gen == gen) { __nanosleep(32); }
        }
        __threadfence();
    }
    __syncthreads();
}

// ------------------------- phase A: word GEMM (f32x2) -----------------------
// C[16384][1024] = A[16384][512] @ W[512][1024] + bias
// tile 128 rows x 64 cols, thread = 8 rows x 4 cols (2 f32x2 accs per row)
__global__ __launch_bounds__(256) void word_gemm(
    const float* __restrict__ A, const float* __restrict__ Wm,
    const float* __restrict__ bias)
{
    __shared__ float As[32 * 129];                   // [k][row], stride 129
    __shared__ __align__(16) float Bs[32][64];       // [k][col]
    const int tid = threadIdx.x;
    const int tx = tid & 15;        // col quad
    const int ty = tid >> 4;        // row group of 8
    const int rowBase = blockIdx.y * 128;
    const int colBase = blockIdx.x * 64;

    ull acc[8][2];
#pragma unroll
    for (int i = 0; i < 8; i++) { acc[i][0] = 0ull; acc[i][1] = 0ull; }

    for (int k0 = 0; k0 < EE; k0 += 32) {
#pragma unroll
        for (int i = 0; i < 4; i++) {
            int f = tid + i * 256;
            int r = f >> 3, c4 = f & 7;
            float4 v = *(const float4*)(A + (rowBase + r) * EE + k0 + c4 * 4);
            As[(c4 * 4 + 0) * 129 + r] = v.x;
            As[(c4 * 4 + 1) * 129 + r] = v.y;
            As[(c4 * 4 + 2) * 129 + r] = v.z;
            As[(c4 * 4 + 3) * 129 + r] = v.w;
        }
#pragma unroll
        for (int i = 0; i < 2; i++) {
            int f = tid + i * 256;
            int r = f >> 4, c4 = f & 15;
            *(float4*)&Bs[r][c4 * 4] =
                *(const float4*)(Wm + (k0 + r) * TWO_H + colBase + c4 * 4);
        }
        __syncthreads();
#pragma unroll 8
        for (int kk = 0; kk < 32; kk++) {
            const float* ar = As + kk * 129 + ty * 8;
            ulonglong2 w2 = *(const ulonglong2*)&Bs[kk][tx * 4];
#pragma unroll
            for (int i = 0; i < 8; i++) {
                ull xp = pk2(ar[i]);
                acc[i][0] = ffma2(xp, w2.x, acc[i][0]);
                acc[i][1] = ffma2(xp, w2.y, acc[i][1]);
            }
        }
        __syncthreads();
    }

    const int col = colBase + tx * 4;
    float2 b0 = *(const float2*)(bias + col);
    float2 b1 = *(const float2*)(bias + col + 2);
#pragma unroll
    for (int i = 0; i < 8; i++) {
        int row = rowBase + ty * 8 + i;
        float2 v0 = upk(acc[i][0]);
        float2 v1 = upk(acc[i][1]);
        v0.x += b0.x; v0.y += b0.y;
        v1.x += b1.x; v1.y += b1.y;
        *(float2*)&g_tmp[row * TWO_H + col] = v0;
        *(float2*)&g_tmp[row * TWO_H + col + 2] = v1;
    }
}

// ------------------------- phase A: BatchNorm -------------------------------
__global__ void zero_stats()
{
    int ch = blockIdx.x * blockDim.x + threadIdx.x;
    if (ch < TWO_H) { g_sum[ch] = 0.f; g_sumsq[ch] = 0.f; }
}

__global__ __launch_bounds__(256) void bn_stats()
{
    int ch = blockIdx.x * 256 + threadIdx.x;
    int rowBase = blockIdx.y * 64;
    float s = 0.f, q = 0.f;
#pragma unroll 4
    for (int r = 0; r < 64; r++) {
        float v = g_tmp[(rowBase + r) * TWO_H + ch];
        s += v; q += v * v;
    }
    atomicAdd(&g_sum[ch], s);
    atomicAdd(&g_sumsq[ch], q);
}

__global__ void bn_finalize(const float* __restrict__ gamma, const float* __restrict__ beta)
{
    int ch = blockIdx.x * blockDim.x + threadIdx.x;
    if (ch >= TWO_H) return;
    const float invN = 1.0f / (float)NLE;
    float mean = g_sum[ch] * invN;
    float var  = g_sumsq[ch] * invN - mean * mean;
    float sc   = gamma[ch] * rsqrtf(var + 1e-5f);
    g_scale[ch] = sc;
    g_shift[ch] = beta[ch] - mean * sc;
}

__global__ __launch_bounds__(256) void bn_apply()
{
    int idx = blockIdx.x * 256 + threadIdx.x;
    int row = idx >> 10;
    int ch  = idx & 1023;
    float v = g_tmp[idx] * g_scale[ch] + g_shift[ch];
    if (ch < HH) g_hbuf[row * HH + ch] = v;
    else         g_cbuf[row * HH + (ch - HH)] = v;
}

// ------------------------- metadata: tree + level buckets -------------------
__global__ void meta_kernel(const int* __restrict__ trans)
{
    __shared__ int cnt[132];
    __shared__ int cur[132];
    __shared__ int smax;
    int b = threadIdx.x;
    for (int i = b; i < 132; i += 128) cnt[i] = 0;
    if (b == 0) smax = 0;
    __syncthreads();

    int sid[130];
    int slv[130];
    int nlv[NN];
    int ptr = 0, bp = 0, n = 0;
    for (int t = 0; t < TT; t++) {
        int act = trans[b * TT + t];
        if (act == 2) {                       // SHIFT
            sid[ptr] = bp; slv[ptr] = 0; ptr++; bp++;
        } else if (act == 3) {                // REDUCE
            int lv = max(slv[ptr - 2], slv[ptr - 1]) + 1;
            g_ch[b * NN + n] = make_int2(sid[ptr - 2], sid[ptr - 1]);
            nlv[n] = lv;
            sid[ptr - 2] = 128 + n; slv[ptr - 2] = lv;
            ptr--; n++;
        }
    }
    g_fin[b] = sid[0];

    int mymax = 0;
    for (int i = 0; i < n; i++) {
        atomicAdd(&cnt[nlv[i]], 1);
        mymax = max(mymax, nlv[i]);
    }
    atomicMax(&smax, mymax);
    __syncthreads();
    if (b == 0) {
        int a = 0;
        for (int lv = 0; lv <= 130; lv++) {
            cur[lv] = a;
            g_lv_start[lv] = a;
            a += cnt[lv];
        }
        g_lv_start[131] = a;
        g_maxlvl = smax;
    }
    __syncthreads();
    for (int i = 0; i < n; i++) {
        int idx = atomicAdd(&cur[nlv[i]], 1);
        g_items[idx] = (b << 7) | i;
    }
}

// ------------------------- persistent level-scan kernel ---------------------
// Tile: 128 nodes x (32 cols x 5 gates); thread = 4 nodes x (4 cols x 5 gates).
// Xs transposed [k][node] stride 129 (conflict-free staging + loads).
// Split factor sv in {1,2,4,8}; each unit does 32/sv K-chunks of 32.
__global__ __launch_bounds__(256) void scan_kernel(
    const float* __restrict__ W, const float* __restrict__ rb, int nblk)
{
    __shared__ float Xs[32 * 129];                     // [k][node] 16.5KB
    __shared__ __align__(16) float Ws[32 * 5 * 32];    // [k][gate][c] 20KB
    __shared__ const float* sm_hl[128];
    __shared__ const float* sm_hr[128];
    __shared__ const float* sm_cl[128];
    __shared__ const float* sm_cr[128];
    __shared__ int sm_out[128];   // node slot (b*NN+n) or -1
    __shared__ int sm_idx[128];   // level-local index or -1

    const int tid = threadIdx.x;
    const int ng = tid >> 3;      // 0..31 -> nodes ng*4 .. ng*4+3
    const int jg = tid & 7;       // col quad
    const int maxlvl = g_maxlvl;

    for (int lv = 1; lv <= maxlvl; lv++) {
        const int start = g_lv_start[lv];
        const int M = g_lv_start[lv + 1] - start;
        if (M <= 0) { grid_barrier(nblk); continue; }

        const int mtiles = (M + 127) >> 7;
        const int base_tiles = mtiles * 16;
        int sv = 1;
        while (sv < PS && base_tiles * (sv << 1) <= nblk) sv <<= 1;
        const int cpu = 32 / sv;                  // chunks per unit
        const int units = base_tiles * sv;

        for (int u = blockIdx.x; u < units; u += nblk) {
            const int tile = u % base_tiles;
            const int split = u / base_tiles;
            const int jt = tile & 15;
            const int mt = tile >> 4;
            const int c0 = split * cpu, c1 = c0 + cpu;

            if (tid < 128) {
                int gi = start + mt * 128 + tid;
                bool valid = gi < start + M;
                int item = g_items[valid ? gi : start];
                int b = item >> 7, n = item & 127;
                int2 ch = g_ch[b * NN + n];
                sm_hl[tid] = hsrc(b, ch.x);
                sm_hr[tid] = hsrc(b, ch.y);
                sm_cl[tid] = csrc(b, ch.x);
                sm_cr[tid] = csrc(b, ch.y);
                sm_out[tid] = valid ? (b * NN + n) : -1;
                sm_idx[tid] = valid ? (mt * 128 + tid) : -1;
            }
            __syncthreads();

            ull acc[4][2][5];
#pragma unroll
            for (int s = 0; s < 4; s++)
#pragma unroll
                for (int p = 0; p < 2; p++)
#pragma unroll
                    for (int g = 0; g < 5; g++) acc[s][p][g] = 0ull;

            float4 xr[4];
            float4 wr[5];
            // prefetch first chunk
            {
                const int kc0 = c0 * 32;
                const bool left = kc0 < HH;
                const int koff = left ? kc0 : (kc0 - HH);
#pragma unroll
                for (int i = 0; i < 4; i++) {
                    int f = tid + i * 256;
                    int r = f >> 3, c4 = f & 7;
                    const float* base = (left ? sm_hl[r] : sm_hr[r]) + koff;
                    xr[i] = *(const float4*)(base + c4 * 4);
                }
#pragma unroll
                for (int i = 0; i < 5; i++) {
                    int f4 = tid + i * 256;
                    int c4 = f4 & 7, g = (f4 >> 3) % 5, k = f4 / 40;
                    wr[i] = *(const float4*)(W + (kc0 + k) * FIVE_H + g * HH + jt * 32 + c4 * 4);
                }
            }

            for (int chk = c0; chk < c1; chk++) {
                // stage regs -> smem (Xs transposed, conflict-free at stride 129)
#pragma unroll
                for (int i = 0; i < 4; i++) {
                    int f = tid + i * 256;
                    int r = f >> 3, c4 = f & 7;
                    Xs[(c4 * 4 + 0) * 129 + r] = xr[i].x;
                    Xs[(c4 * 4 + 1) * 129 + r] = xr[i].y;
                    Xs[(c4 * 4 + 2) * 129 + r] = xr[i].z;
                    Xs[(c4 * 4 + 3) * 129 + r] = xr[i].w;
                }
#pragma unroll
                for (int i = 0; i < 5; i++)
                    *(float4*)&Ws[(tid + i * 256) * 4] = wr[i];
                __syncthreads();

                if (chk + 1 < c1) {
                    const int kc0 = (chk + 1) * 32;
                    const bool left = kc0 < HH;
                    const int koff = left ? kc0 : (kc0 - HH);
#pragma unroll
                    for (int i = 0; i < 4; i++) {
                        int f = tid + i * 256;
                        int r = f >> 3, c4 = f & 7;
                        const float* base = (left ? sm_hl[r] : sm_hr[r]) + koff;
                        xr[i] = *(const float4*)(base + c4 * 4);
                    }
#pragma unroll
                    for (int i = 0; i < 5; i++) {
                        int f4 = tid + i * 256;
                        int c4 = f4 & 7, g = (f4 >> 3) % 5, k = f4 / 40;
                        wr[i] = *(const float4*)(W + (kc0 + k) * FIVE_H + g * HH + jt * 32 + c4 * 4);
                    }
                }

#pragma unroll 8
                for (int k = 0; k < 32; k++) {
                    const float* xrow = Xs + k * 129 + ng * 4;
                    ull xp0 = pk2(xrow[0]);
                    ull xp1 = pk2(xrow[1]);
                    ull xp2 = pk2(xrow[2]);
                    ull xp3 = pk2(xrow[3]);
#pragma unroll
                    for (int g = 0; g < 5; g++) {
                        ulonglong2 w = *(const ulonglong2*)&Ws[(k * 5 + g) * 32 + jg * 4];
                        acc[0][0][g] = ffma2(xp0, w.x, acc[0][0][g]);
                        acc[0][1][g] = ffma2(xp0, w.y, acc[0][1][g]);
                        acc[1][0][g] = ffma2(xp1, w.x, acc[1][0][g]);
                        acc[1][1][g] = ffma2(xp1, w.y, acc[1][1][g]);
                        acc[2][0][g] = ffma2(xp2, w.x, acc[2][0][g]);
                        acc[2][1][g] = ffma2(xp2, w.y, acc[2][1][g]);
                        acc[3][0][g] = ffma2(xp3, w.x, acc[3][0][g]);
                        acc[3][1][g] = ffma2(xp3, w.y, acc[3][1][g]);
                    }
                }
                __syncthreads();
            }

            if (sv == 1) {
                // fused epilogue, all 5 gates in registers
#pragma unroll
                for (int s = 0; s < 4; s++) {
                    int r = ng * 4 + s;
                    int o = sm_out[r];
                    if (o < 0) continue;
                    const float* clp = sm_cl[r];
                    const float* crp = sm_cr[r];
#pragma unroll
                    for (int p = 0; p < 2; p++) {
                        int col = jt * 32 + jg * 4 + p * 2;
                        float2 vi  = upk(acc[s][p][0]);
                        float2 vfl = upk(acc[s][p][1]);
                        float2 vfr = upk(acc[s][p][2]);
                        float2 vo  = upk(acc[s][p][3]);
                        float2 vg  = upk(acc[s][p][4]);
                        float2 bi  = *(const float2*)(rb + 0 * HH + col);
                        float2 bfl = *(const float2*)(rb + 1 * HH + col);
                        float2 bfr = *(const float2*)(rb + 2 * HH + col);
                        float2 bo  = *(const float2*)(rb + 3 * HH + col);
                        float2 bg  = *(const float2*)(rb + 4 * HH + col);
                        float2 cl = *(const float2*)(clp + col);
                        float2 cr = *(const float2*)(crp + col);
                        float2 c, h;
                        c.x = sigf(vfl.x + bfl.x) * cl.x + sigf(vfr.x + bfr.x) * cr.x
                            + sigf(vi.x + bi.x) * tanhf(vg.x + bg.x);
                        c.y = sigf(vfl.y + bfl.y) * cl.y + sigf(vfr.y + bfr.y) * cr.y
                            + sigf(vi.y + bi.y) * tanhf(vg.y + bg.y);
                        h.x = sigf(vo.x + bo.x) * tanhf(c.x);
                        h.y = sigf(vo.y + bo.y) * tanhf(c.y);
                        *(float2*)&g_node_h[o * HH + col] = h;
                        *(float2*)&g_node_c[o * HH + col] = c;
                    }
                }
            } else {
                // write split-K partials
#pragma unroll
                for (int s = 0; s < 4; s++) {
                    int r = ng * 4 + s;
                    int idx = sm_idx[r];
                    if (idx < 0) continue;
#pragma unroll
                    for (int p = 0; p < 2; p++) {
                        int col = jt * 32 + jg * 4 + p * 2;
#pragma unroll
                        for (int g = 0; g < 5; g++) {
                            float2 v = upk(acc[s][p][g]);
                            int base = (idx * FIVE_H + g * HH + col) * PS + split;
                            g_part[base] = v.x;
                            g_part[base + PS] = v.y;
                        }
                    }
                }
            }
            __syncthreads();
        }
        grid_barrier(nblk);

        if (sv > 1) {
            // reduce partials (fixed order) + LSTM epilogue
            int total2 = M * HH;
            for (int f = blockIdx.x * 256 + tid; f < total2; f += nblk * 256) {
                int j = f & 511, i = f >> 9;
                int item = g_items[start + i];
                int b = item >> 7, n = item & 127;
                int2 ch = g_ch[b * NN + n];
                float ga[5];
#pragma unroll
                for (int g = 0; g < 5; g++) {
                    int base = (i * FIVE_H + g * HH + j) * PS;
                    float s = 0.f;
                    for (int t = 0; t < sv; t++) s += g_part[base + t];
                    ga[g] = s + rb[g * HH + j];
                }
                float cl = csrc(b, ch.x)[j];
                float cr = csrc(b, ch.y)[j];
                float c = sigf(ga[1]) * cl + sigf(ga[2]) * cr + sigf(ga[0]) * tanhf(ga[4]);
                float h = sigf(ga[3]) * tanhf(c);
                int o = b * NN + n;
                g_node_h[o * HH + j] = h;
                g_node_c[o * HH + j] = c;
            }
            grid_barrier(nblk);
        }
    }
}

// ------------------------- final readout ------------------------------------
__global__ void final_kernel(float* __restrict__ out)
{
    int idx = blockIdx.x * blockDim.x + threadIdx.x;
    if (idx >= BB * HH) return;
    int b = idx >> 9;
    int j = idx & 511;
    int root = g_fin[b] - 128;
    out[idx] = g_node_h[(b * NN + root) * HH + j];
}

// ------------------------- launch -------------------------------------------
extern "C" void kernel_launch(void* const* d_in, const int* in_sizes, int n_in,
                              void* d_out, int out_size)
{
    const float* sentence    = (const float*)d_in[0];
    const int*   transitions = (const int*)  d_in[1];
    const float* word_W      = (const float*)d_in[2];
    const float* word_b      = (const float*)d_in[3];
    const float* bn_gamma    = (const float*)d_in[4];
    const float* bn_beta     = (const float*)d_in[5];
    const float* reduce_W    = (const float*)d_in[6];
    const float* reduce_b    = (const float*)d_in[7];
    float* out = (float*)d_out;

    int dev = 0, nsm = 148;
    cudaGetDevice(&dev);
    cudaDeviceGetAttribute(&nsm, cudaDevAttrMultiProcessorCount, dev);

    word_gemm<<<dim3(TWO_H / 64, NLE / 128), 256>>>(sentence, word_W, word_b);
    zero_stats<<<4, 256>>>();
    bn_stats<<<dim3(4, 256), 256>>>();
    bn_finalize<<<4, 256>>>(bn_gamma, bn_beta);
    bn_apply<<<(NLE * TWO_H) / 256, 256>>>();

    meta_kernel<<<1, 128>>>(transitions);

    scan_kernel<<<nsm, 256>>>(reduce_W, reduce_b, nsm);

    final_kernel<<<(BB * HH + 255) / 256, 256>>>(out);
}

// round 9
// speedup vs baseline: 2.8599x; 1.0050x over previous
#include <cuda_runtime.h>
#include <cuda_bf16.h>
#include <math.h>

typedef unsigned long long ull;
typedef unsigned int uint;

// ---------------------------------------------------------------------------
// SPINN TreeLSTM: level-scheduled tree evaluation.
//   Big levels (M>128): mma.sync bf16x3 (fp32-faithful) tensor path.
//   Small levels:       FFMA2 split-K SIMT path.
// B=128, L=128, E=512, H=512, nodes/row NN=127.
// ---------------------------------------------------------------------------

#define BB 128
#define LL 128
#define EE 512
#define HH 512
#define TT 255
#define NN 127
#define TWO_H 1024
#define FIVE_H 2560
#define NLE (BB*LL)
#define PS 8

// dynamic smem layout (16B-aligned base):
//   two chunk buffers of 40960B: [AH 10240 | AL 10240 | BH 10240 | BL 10240]
//   (A/B tiles are 128 rows x 40 bf16, stride 80B)
#define GBUF   40960
#define A_LO   10240
#define B_HI   20480
#define B_LO   30720
#define CTRL_OFF 81920
#define SMEM_SZ  90112

struct Ctrl {
    const float* hl[128];
    const float* hr[128];
    const float* cl[128];
    const float* cr[128];
    int  out[128];
    int  idx[128];
};

// ------------------------- scratch (static device memory) ------------------
__device__ float g_tmp[NLE * TWO_H];
__device__ float g_hbuf[BB * LL * HH];
__device__ float g_cbuf[BB * LL * HH];
__device__ float g_node_h[BB * NN * HH];
__device__ float g_node_c[BB * NN * HH];
__device__ float g_gates[8192 * FIVE_H];           // tensor-path gate preacts
__device__ float g_part[128 * FIVE_H * PS];        // small-path split-K partials
__device__ __nv_bfloat16 g_wb_hi[FIVE_H * TWO_H];  // W bf16 hi, [n][k]
__device__ __nv_bfloat16 g_wb_lo[FIVE_H * TWO_H];  // W bf16 lo, [n][k]
__device__ __nv_bfloat16 g_xa_hi[8192 * TWO_H];    // level x bf16 hi, [idx][k]
__device__ __nv_bfloat16 g_xa_lo[8192 * TWO_H];    // level x bf16 lo
__device__ float g_sum[TWO_H];
__device__ float g_sumsq[TWO_H];
__device__ float g_scale[TWO_H];
__device__ float g_shift[TWO_H];
__device__ int2  g_ch[BB * NN];
__device__ int   g_items[BB * NN];
__device__ int   g_lv_start[132];
__device__ int   g_maxlvl;
__device__ int   g_fin[BB];
__device__ int            g_bar_count;
__device__ volatile int   g_bar_gen;

__device__ __forceinline__ float sigf(float x) { return 1.0f / (1.0f + expf(-x)); }

__device__ __forceinline__ ull ffma2(ull x, ull w, ull a) {
    asm("fma.rn.f32x2 %0, %1, %2, %0;" : "+l"(a) : "l"(x), "l"(w));
    return a;
}
__device__ __forceinline__ ull pk2(float v) {
    ull r; asm("mov.b64 %0, {%1, %2};" : "=l"(r) : "f"(v), "f"(v)); return r;
}
__device__ __forceinline__ float2 upk(ull v) {
    float2 f; asm("mov.b64 {%0, %1}, %2;" : "=f"(f.x), "=f"(f.y) : "l"(v)); return f;
}

// mma.sync m16n8k16 row.col f32.bf16.bf16.f32 (base-target HMMA)
__device__ __forceinline__ void mma_bf16(float* c, uint a0, uint a1, uint a2, uint a3,
                                         uint b0, uint b1) {
    asm volatile("mma.sync.aligned.m16n8k16.row.col.f32.bf16.bf16.f32 "
                 "{%0,%1,%2,%3}, {%4,%5,%6,%7}, {%8,%9}, {%0,%1,%2,%3};"
                 : "+f"(c[0]), "+f"(c[1]), "+f"(c[2]), "+f"(c[3])
                 : "r"(a0), "r"(a1), "r"(a2), "r"(a3), "r"(b0), "r"(b1));
}

__device__ __forceinline__ void cvt2(float a, float b, uint &hp, uint &lp) {
    __nv_bfloat16 ha = __float2bfloat16(a), hb = __float2bfloat16(b);
    float ra = a - __bfloat162float(ha);
    float rb2 = b - __bfloat162float(hb);
    __nv_bfloat16 la = __float2bfloat16(ra), lb = __float2bfloat16(rb2);
    hp = (uint)*(unsigned short*)&ha | ((uint)*(unsigned short*)&hb << 16);
    lp = (uint)*(unsigned short*)&la | ((uint)*(unsigned short*)&lb << 16);
}

__device__ __forceinline__ const float* hsrc(int b, int id) {
    return (id < 128) ? (g_hbuf + (b * LL + id) * HH)
                      : (g_node_h + (b * NN + (id - 128)) * HH);
}
__device__ __forceinline__ const float* csrc(int b, int id) {
    return (id < 128) ? (g_cbuf + (b * LL + id) * HH)
                      : (g_node_c + (b * NN + (id - 128)) * HH);
}

__device__ __forceinline__ void grid_barrier(int nblk) {
    __syncthreads();
    if (threadIdx.x == 0) {
        __threadfence();
        int gen = g_bar_gen;
        if (atomicAdd(&g_bar_count, 1) == nblk - 1) {
            g_bar_count = 0;
            __threadfence();
            g_bar_gen = gen + 1;
        } else {
            while (g_bar_gen == gen) { __nanosleep(32); }
        }
        __threadfence();
    }
    __syncthreads();
}

// ------------------------- phase A: word GEMM (f32x2) -----------------------
__global__ __launch_bounds__(256) void word_gemm(
    const float* __restrict__ A, const float* __restrict__ Wm,
    const float* __restrict__ bias)
{
    __shared__ float As[32 * 129];
    __shared__ __align__(16) float Bs[32][64];
    const int tid = threadIdx.x;
    const int tx = tid & 15;
    const int ty = tid >> 4;
    const int rowBase = blockIdx.y * 128;
    const int colBase = blockIdx.x * 64;

    ull acc[8][2];
#pragma unroll
    for (int i = 0; i < 8; i++) { acc[i][0] = 0ull; acc[i][1] = 0ull; }

    for (int k0 = 0; k0 < EE; k0 += 32) {
#pragma unroll
        for (int i = 0; i < 4; i++) {
            int f = tid + i * 256;
            int r = f >> 3, c4 = f & 7;
            float4 v = *(const float4*)(A + (rowBase + r) * EE + k0 + c4 * 4);
            As[(c4 * 4 + 0) * 129 + r] = v.x;
            As[(c4 * 4 + 1) * 129 + r] = v.y;
            As[(c4 * 4 + 2) * 129 + r] = v.z;
            As[(c4 * 4 + 3) * 129 + r] = v.w;
        }
#pragma unroll
        for (int i = 0; i < 2; i++) {
            int f = tid + i * 256;
            int r = f >> 4, c4 = f & 15;
            *(float4*)&Bs[r][c4 * 4] =
                *(const float4*)(Wm + (k0 + r) * TWO_H + colBase + c4 * 4);
        }
        __syncthreads();
#pragma unroll 8
        for (int kk = 0; kk < 32; kk++) {
            const float* ar = As + kk * 129 + ty * 8;
            ulonglong2 w2 = *(const ulonglong2*)&Bs[kk][tx * 4];
#pragma unroll
            for (int i = 0; i < 8; i++) {
                ull xp = pk2(ar[i]);
                acc[i][0] = ffma2(xp, w2.x, acc[i][0]);
                acc[i][1] = ffma2(xp, w2.y, acc[i][1]);
            }
        }
        __syncthreads();
    }

    const int col = colBase + tx * 4;
    float2 b0 = *(const float2*)(bias + col);
    float2 b1 = *(const float2*)(bias + col + 2);
#pragma unroll
    for (int i = 0; i < 8; i++) {
        int row = rowBase + ty * 8 + i;
        float2 v0 = upk(acc[i][0]);
        float2 v1 = upk(acc[i][1]);
        v0.x += b0.x; v0.y += b0.y;
        v1.x += b1.x; v1.y += b1.y;
        *(float2*)&g_tmp[row * TWO_H + col] = v0;
        *(float2*)&g_tmp[row * TWO_H + col + 2] = v1;
    }
}

// ------------------------- phase A: BatchNorm -------------------------------
__global__ void zero_stats()
{
    int ch = blockIdx.x * blockDim.x + threadIdx.x;
    if (ch < TWO_H) { g_sum[ch] = 0.f; g_sumsq[ch] = 0.f; }
}

__global__ __launch_bounds__(256) void bn_stats()
{
    int ch = blockIdx.x * 256 + threadIdx.x;
    int rowBase = blockIdx.y * 64;
    float s = 0.f, q = 0.f;
#pragma unroll 4
    for (int r = 0; r < 64; r++) {
        float v = g_tmp[(rowBase + r) * TWO_H + ch];
        s += v; q += v * v;
    }
    atomicAdd(&g_sum[ch], s);
    atomicAdd(&g_sumsq[ch], q);
}

__global__ void bn_finalize(const float* __restrict__ gamma, const float* __restrict__ beta)
{
    int ch = blockIdx.x * blockDim.x + threadIdx.x;
    if (ch >= TWO_H) return;
    const float invN = 1.0f / (float)NLE;
    float mean = g_sum[ch] * invN;
    float var  = g_sumsq[ch] * invN - mean * mean;
    float sc   = gamma[ch] * rsqrtf(var + 1e-5f);
    g_scale[ch] = sc;
    g_shift[ch] = beta[ch] - mean * sc;
}

__global__ __launch_bounds__(256) void bn_apply()
{
    int idx = blockIdx.x * 256 + threadIdx.x;
    int row = idx >> 10;
    int ch  = idx & 1023;
    float v = g_tmp[idx] * g_scale[ch] + g_shift[ch];
    if (ch < HH) g_hbuf[row * HH + ch] = v;
    else         g_cbuf[row * HH + (ch - HH)] = v;
}

// ------------------------- W preprocessing: bf16 hi/lo, [n][k] --------------
__global__ __launch_bounds__(256) void wprep(const float* __restrict__ W)
{
    int f = blockIdx.x * 256 + threadIdx.x;      // f = k*2560 + n (coalesced read)
    if (f >= TWO_H * FIVE_H) return;
    int k = f / FIVE_H, n = f - k * FIVE_H;
    float w = W[f];
    __nv_bfloat16 hb = __float2bfloat16(w);
    float rest = w - __bfloat162float(hb);
    __nv_bfloat16 lb = __float2bfloat16(rest);
    g_wb_hi[n * TWO_H + k] = hb;
    g_wb_lo[n * TWO_H + k] = lb;
}

// ------------------------- metadata: tree + level buckets -------------------
__global__ void meta_kernel(const int* __restrict__ trans)
{
    __shared__ int cnt[132];
    __shared__ int cur[132];
    __shared__ int smax;
    int b = threadIdx.x;
    for (int i = b; i < 132; i += 128) cnt[i] = 0;
    if (b == 0) smax = 0;
    __syncthreads();

    int sid[130];
    int slv[130];
    int nlv[NN];
    int ptr = 0, bp = 0, n = 0;
    for (int t = 0; t < TT; t++) {
        int act = trans[b * TT + t];
        if (act == 2) {
            sid[ptr] = bp; slv[ptr] = 0; ptr++; bp++;
        } else if (act == 3) {
            int lv = max(slv[ptr - 2], slv[ptr - 1]) + 1;
            g_ch[b * NN + n] = make_int2(sid[ptr - 2], sid[ptr - 1]);
            nlv[n] = lv;
            sid[ptr - 2] = 128 + n; slv[ptr - 2] = lv;
            ptr--; n++;
        }
    }
    g_fin[b] = sid[0];

    int mymax = 0;
    for (int i = 0; i < n; i++) {
        atomicAdd(&cnt[nlv[i]], 1);
        mymax = max(mymax, nlv[i]);
    }
    atomicMax(&smax, mymax);
    __syncthreads();
    if (b == 0) {
        int a = 0;
        for (int lv = 0; lv <= 130; lv++) {
            cur[lv] = a;
            g_lv_start[lv] = a;
            a += cnt[lv];
        }
        g_lv_start[131] = a;
        g_maxlvl = smax;
    }
    __syncthreads();
    for (int i = 0; i < n; i++) {
        int idx = atomicAdd(&cur[nlv[i]], 1);
        g_items[idx] = (b << 7) | i;
    }
}

// ------------------------- persistent level-scan kernel ---------------------
extern __shared__ char dsm_raw[];

__global__ __launch_bounds__(256) void scan_kernel(
    const float* __restrict__ W, const float* __restrict__ rb, int nblk)
{
    const int tid = threadIdx.x;
    const int lane = tid & 31;
    const int wid = tid >> 5;
    const int wm = wid >> 1;           // 0..3 : warp m-block (32 rows)
    const int wn = wid & 1;            // 0..1 : warp n-block (64 cols)
    const int g = lane >> 2;           // fragment group row
    const int tig = lane & 3;          // thread-in-group

    // 16B-aligned dynamic smem base
    char* base = dsm_raw;
    Ctrl* C = (Ctrl*)(base + CTRL_OFF);
    float* Xs = (float*)(base);            // small path: 16.5KB (aliases buffers)
    float* Ws = (float*)(base + 16896);    // small path: 20KB

    const int maxlvl = g_maxlvl;

    for (int lv = 1; lv <= maxlvl; lv++) {
        const int start = g_lv_start[lv];
        const int M = g_lv_start[lv + 1] - start;
        if (M <= 0) { grid_barrier(nblk); continue; }

        if (M > 128) {
            // ======== tensor path: per-level x -> bf16 hi/lo conversion =====
            int totalc = M * 64;                 // 16 elems per work item
            for (int u = blockIdx.x * 256 + tid; u < totalc; u += nblk * 256) {
                int i = u >> 6;
                int kq = (u & 63) << 4;
                int item = g_items[start + i];
                int b = item >> 7, n = item & 127;
                int2 ch = g_ch[b * NN + n];
                const float* src = (kq < HH) ? (hsrc(b, ch.x) + kq)
                                             : (hsrc(b, ch.y) + kq - HH);
                char* dh = (char*)(g_xa_hi + i * TWO_H + kq);
                char* dl = (char*)(g_xa_lo + i * TWO_H + kq);
#pragma unroll
                for (int q = 0; q < 4; q++) {
                    float4 v = *(const float4*)(src + q * 4);
                    uint h0, h1, l0, l1;
                    cvt2(v.x, v.y, h0, l0);
                    cvt2(v.z, v.w, h1, l1);
                    *(uint2*)(dh + q * 8) = make_uint2(h0, h1);
                    *(uint2*)(dl + q * 8) = make_uint2(l0, l1);
                }
            }
            grid_barrier(nblk);

            // ======== mma units: 128m x 128n tiles, K=1024 in 32-chunks =====
            const int mtiles = (M + 127) >> 7;
            const int units = mtiles * 20;
            const int r2 = tid >> 1, hf = tid & 1;      // staging coords
            for (int u = blockIdx.x; u < units; u += nblk) {
                const int mt = u / 20;
                const int nt = u - mt * 20;

                // stage chunk 0 into buffer 0
                {
                    char* bp = base;
                    const char* sa_h = (const char*)(g_xa_hi + (mt * 128 + r2) * TWO_H + hf * 16);
                    const char* sa_l = (const char*)(g_xa_lo + (mt * 128 + r2) * TWO_H + hf * 16);
                    const char* sb_h = (const char*)(g_wb_hi + (nt * 128 + r2) * TWO_H + hf * 16);
                    const char* sb_l = (const char*)(g_wb_lo + (nt * 128 + r2) * TWO_H + hf * 16);
                    int d = r2 * 80 + hf * 32;
                    *(uint4*)(bp + d)               = *(const uint4*)(sa_h);
                    *(uint4*)(bp + d + 16)          = *(const uint4*)(sa_h + 16);
                    *(uint4*)(bp + A_LO + d)        = *(const uint4*)(sa_l);
                    *(uint4*)(bp + A_LO + d + 16)   = *(const uint4*)(sa_l + 16);
                    *(uint4*)(bp + B_HI + d)        = *(const uint4*)(sb_h);
                    *(uint4*)(bp + B_HI + d + 16)   = *(const uint4*)(sb_h + 16);
                    *(uint4*)(bp + B_LO + d)        = *(const uint4*)(sb_l);
                    *(uint4*)(bp + B_LO + d + 16)   = *(const uint4*)(sb_l + 16);
                }
                __syncthreads();

                float acc[2][8][4];
#pragma unroll
                for (int mf = 0; mf < 2; mf++)
#pragma unroll
                    for (int nf = 0; nf < 8; nf++)
#pragma unroll
                        for (int q = 0; q < 4; q++) acc[mf][nf][q] = 0.f;

                for (int chk = 0; chk < 32; chk++) {
                    char* cur = base + (chk & 1) * GBUF;
                    char* nxt = base + ((chk + 1) & 1) * GBUF;

                    // prefetch next chunk (LDG latency hidden by mma below)
                    uint4 pa[4], pb[4];
                    if (chk < 31) {
                        int ko = (chk + 1) * 32 + hf * 16;
                        const char* sa_h = (const char*)(g_xa_hi + (mt * 128 + r2) * TWO_H + ko);
                        const char* sa_l = (const char*)(g_xa_lo + (mt * 128 + r2) * TWO_H + ko);
                        const char* sb_h = (const char*)(g_wb_hi + (nt * 128 + r2) * TWO_H + ko);
                        const char* sb_l = (const char*)(g_wb_lo + (nt * 128 + r2) * TWO_H + ko);
                        pa[0] = *(const uint4*)(sa_h);     pa[1] = *(const uint4*)(sa_h + 16);
                        pa[2] = *(const uint4*)(sa_l);     pa[3] = *(const uint4*)(sa_l + 16);
                        pb[0] = *(const uint4*)(sb_h);     pb[1] = *(const uint4*)(sb_h + 16);
                        pb[2] = *(const uint4*)(sb_l);     pb[3] = *(const uint4*)(sb_l + 16);
                    }

                    // compute on cur
                    const char* AH = cur;
                    const char* AL = cur + A_LO;
                    const char* BH = cur + B_HI;
                    const char* BL = cur + B_LO;
#pragma unroll
                    for (int kk = 0; kk < 32; kk += 16) {
                        const int co = (kk + 2 * tig) * 2;
                        uint bh[8][2], bl[8][2];
#pragma unroll
                        for (int nf = 0; nf < 8; nf++) {
                            int nrow = wn * 64 + nf * 8 + g;
                            bh[nf][0] = *(const uint*)(BH + nrow * 80 + co);
                            bh[nf][1] = *(const uint*)(BH + nrow * 80 + co + 16);
                            bl[nf][0] = *(const uint*)(BL + nrow * 80 + co);
                            bl[nf][1] = *(const uint*)(BL + nrow * 80 + co + 16);
                        }
#pragma unroll
                        for (int mf = 0; mf < 2; mf++) {
                            int mrow = wm * 32 + mf * 16 + g;
                            uint a0 = *(const uint*)(AH + mrow * 80 + co);
                            uint a1 = *(const uint*)(AH + (mrow + 8) * 80 + co);
                            uint a2 = *(const uint*)(AH + mrow * 80 + co + 16);
                            uint a3 = *(const uint*)(AH + (mrow + 8) * 80 + co + 16);
                            uint l0 = *(const uint*)(AL + mrow * 80 + co);
                            uint l1 = *(const uint*)(AL + (mrow + 8) * 80 + co);
                            uint l2 = *(const uint*)(AL + mrow * 80 + co + 16);
                            uint l3 = *(const uint*)(AL + (mrow + 8) * 80 + co + 16);
#pragma unroll
                            for (int nf = 0; nf < 8; nf++) {
                                mma_bf16(acc[mf][nf], a0, a1, a2, a3, bh[nf][0], bh[nf][1]);
                                mma_bf16(acc[mf][nf], l0, l1, l2, l3, bh[nf][0], bh[nf][1]);
                                mma_bf16(acc[mf][nf], a0, a1, a2, a3, bl[nf][0], bl[nf][1]);
                            }
                        }
                    }

                    if (chk < 31) {
                        int d = r2 * 80 + hf * 32;
                        *(uint4*)(nxt + d)             = pa[0];
                        *(uint4*)(nxt + d + 16)        = pa[1];
                        *(uint4*)(nxt + A_LO + d)      = pa[2];
                        *(uint4*)(nxt + A_LO + d + 16) = pa[3];
                        *(uint4*)(nxt + B_HI + d)      = pb[0];
                        *(uint4*)(nxt + B_HI + d + 16) = pb[1];
                        *(uint4*)(nxt + B_LO + d)      = pb[2];
                        *(uint4*)(nxt + B_LO + d + 16) = pb[3];
                    }
                    __syncthreads();
                }

                // write accumulators to gate buffer
#pragma unroll
                for (int mf = 0; mf < 2; mf++) {
                    int row = wm * 32 + mf * 16 + g;
                    int gi = mt * 128 + row;
                    float* dst0 = g_gates + (size_t)gi * FIVE_H;
#pragma unroll
                    for (int nf = 0; nf < 8; nf++) {
                        int col = nt * 128 + wn * 64 + nf * 8 + 2 * tig;
                        *(float2*)(dst0 + col) =
                            make_float2(acc[mf][nf][0], acc[mf][nf][1]);
                        *(float2*)(dst0 + 8 * FIVE_H + col) =
                            make_float2(acc[mf][nf][2], acc[mf][nf][3]);
                    }
                }
            }
            grid_barrier(nblk);

            // epilogue: bias + TreeLSTM from g_gates
            for (int f = blockIdx.x * 256 + tid; f < M * HH; f += nblk * 256) {
                int j = f & 511, i = f >> 9;
                int item = g_items[start + i];
                int b = item >> 7, n = item & 127;
                int2 ch = g_ch[b * NN + n];
                const float* gg = g_gates + (size_t)i * FIVE_H;
                float ai  = gg[0 * HH + j] + rb[0 * HH + j];
                float afl = gg[1 * HH + j] + rb[1 * HH + j];
                float afr = gg[2 * HH + j] + rb[2 * HH + j];
                float ao  = gg[3 * HH + j] + rb[3 * HH + j];
                float ag  = gg[4 * HH + j] + rb[4 * HH + j];
                float cl = csrc(b, ch.x)[j];
                float cr = csrc(b, ch.y)[j];
                float c = sigf(afl) * cl + sigf(afr) * cr + sigf(ai) * tanhf(ag);
                float h = sigf(ao) * tanhf(c);
                int o = b * NN + n;
                g_node_h[o * HH + j] = h;
                g_node_c[o * HH + j] = c;
            }
            grid_barrier(nblk);
        } else {
            // ================= small path: FFMA2 split-K ====================
            const int base_tiles = 16;
            int sv = 1;
            while (sv < PS && base_tiles * (sv << 1) <= nblk) sv <<= 1;
            const int cpu = 32 / sv;
            const int units = base_tiles * sv;
            const int ng = tid >> 3, jg = tid & 7;

            for (int u = blockIdx.x; u < units; u += nblk) {
                const int tile = u % base_tiles;
                const int split = u / base_tiles;
                const int jt = tile & 15;
                const int c0 = split * cpu, c1 = c0 + cpu;

                if (tid < 128) {
                    int gi = start + tid;
                    bool valid = gi < start + M;
                    int item = g_items[valid ? gi : start];
                    int b = item >> 7, n = item & 127;
                    int2 ch = g_ch[b * NN + n];
                    C->hl[tid] = hsrc(b, ch.x);
                    C->hr[tid] = hsrc(b, ch.y);
                    C->cl[tid] = csrc(b, ch.x);
                    C->cr[tid] = csrc(b, ch.y);
                    C->out[tid] = valid ? (b * NN + n) : -1;
                    C->idx[tid] = valid ? tid : -1;
                }
                __syncthreads();

                ull acc[4][2][5];
#pragma unroll
                for (int s = 0; s < 4; s++)
#pragma unroll
                    for (int p = 0; p < 2; p++)
#pragma unroll
                        for (int gg2 = 0; gg2 < 5; gg2++) acc[s][p][gg2] = 0ull;

                float4 xr[4];
                float4 wr[5];
                {
                    const int kc0 = c0 * 32;
                    const bool left = kc0 < HH;
                    const int koff = left ? kc0 : (kc0 - HH);
#pragma unroll
                    for (int i = 0; i < 4; i++) {
                        int f = tid + i * 256;
                        int r = f >> 3, c4 = f & 7;
                        const float* bp2 = (left ? C->hl[r] : C->hr[r]) + koff;
                        xr[i] = *(const float4*)(bp2 + c4 * 4);
                    }
#pragma unroll
                    for (int i = 0; i < 5; i++) {
                        int f4 = tid + i * 256;
                        int c4 = f4 & 7, gg2 = (f4 >> 3) % 5, k = f4 / 40;
                        wr[i] = *(const float4*)(W + (kc0 + k) * FIVE_H + gg2 * HH + jt * 32 + c4 * 4);
                    }
                }

                for (int chk = c0; chk < c1; chk++) {
#pragma unroll
                    for (int i = 0; i < 4; i++) {
                        int f = tid + i * 256;
                        int r = f >> 3, c4 = f & 7;
                        Xs[(c4 * 4 + 0) * 129 + r] = xr[i].x;
                        Xs[(c4 * 4 + 1) * 129 + r] = xr[i].y;
                        Xs[(c4 * 4 + 2) * 129 + r] = xr[i].z;
                        Xs[(c4 * 4 + 3) * 129 + r] = xr[i].w;
                    }
#pragma unroll
                    for (int i = 0; i < 5; i++)
                        *(float4*)&Ws[(tid + i * 256) * 4] = wr[i];
                    __syncthreads();

                    if (chk + 1 < c1) {
                        const int kc0 = (chk + 1) * 32;
                        const bool left = kc0 < HH;
                        const int koff = left ? kc0 : (kc0 - HH);
#pragma unroll
                        for (int i = 0; i < 4; i++) {
                            int f = tid + i * 256;
                            int r = f >> 3, c4 = f & 7;
                            const float* bp2 = (left ? C->hl[r] : C->hr[r]) + koff;
                            xr[i] = *(const float4*)(bp2 + c4 * 4);
                        }
#pragma unroll
                        for (int i = 0; i < 5; i++) {
                            int f4 = tid + i * 256;
                            int c4 = f4 & 7, gg2 = (f4 >> 3) % 5, k = f4 / 40;
                            wr[i] = *(const float4*)(W + (kc0 + k) * FIVE_H + gg2 * HH + jt * 32 + c4 * 4);
                        }
                    }

#pragma unroll 8
                    for (int k = 0; k < 32; k++) {
                        const float* xrow = Xs + k * 129 + ng * 4;
                        ull xp0 = pk2(xrow[0]);
                        ull xp1 = pk2(xrow[1]);
                        ull xp2 = pk2(xrow[2]);
                        ull xp3 = pk2(xrow[3]);
#pragma unroll
                        for (int gg2 = 0; gg2 < 5; gg2++) {
                            ulonglong2 w = *(const ulonglong2*)&Ws[(k * 5 + gg2) * 32 + jg * 4];
                            acc[0][0][gg2] = ffma2(xp0, w.x, acc[0][0][gg2]);
                            acc[0][1][gg2] = ffma2(xp0, w.y, acc[0][1][gg2]);
                            acc[1][0][gg2] = ffma2(xp1, w.x, acc[1][0][gg2]);
                            acc[1][1][gg2] = ffma2(xp1, w.y, acc[1][1][gg2]);
                            acc[2][0][gg2] = ffma2(xp2, w.x, acc[2][0][gg2]);
                            acc[2][1][gg2] = ffma2(xp2, w.y, acc[2][1][gg2]);
                            acc[3][0][gg2] = ffma2(xp3, w.x, acc[3][0][gg2]);
                            acc[3][1][gg2] = ffma2(xp3, w.y, acc[3][1][gg2]);
                        }
                    }
                    __syncthreads();
                }

                if (sv == 1) {
#pragma unroll
                    for (int s = 0; s < 4; s++) {
                        int r = ng * 4 + s;
                        int o = C->out[r];
                        if (o < 0) continue;
                        const float* clp = C->cl[r];
                        const float* crp = C->cr[r];
#pragma unroll
                        for (int p = 0; p < 2; p++) {
                            int col = jt * 32 + jg * 4 + p * 2;
                            float2 vi  = upk(acc[s][p][0]);
                            float2 vfl = upk(acc[s][p][1]);
                            float2 vfr = upk(acc[s][p][2]);
                            float2 vo  = upk(acc[s][p][3]);
                            float2 vg  = upk(acc[s][p][4]);
                            float2 bi  = *(const float2*)(rb + 0 * HH + col);
                            float2 bfl = *(const float2*)(rb + 1 * HH + col);
                            float2 bfr = *(const float2*)(rb + 2 * HH + col);
                            float2 bo  = *(const float2*)(rb + 3 * HH + col);
                            float2 bg  = *(const float2*)(rb + 4 * HH + col);
                            float2 cl = *(const float2*)(clp + col);
                            float2 cr = *(const float2*)(crp + col);
                            float2 c, h;
                            c.x = sigf(vfl.x + bfl.x) * cl.x + sigf(vfr.x + bfr.x) * cr.x
                                + sigf(vi.x + bi.x) * tanhf(vg.x + bg.x);
                            c.y = sigf(vfl.y + bfl.y) * cl.y + sigf(vfr.y + bfr.y) * cr.y
                                + sigf(vi.y + bi.y) * tanhf(vg.y + bg.y);
                            h.x = sigf(vo.x + bo.x) * tanhf(c.x);
                            h.y = sigf(vo.y + bo.y) * tanhf(c.y);
                            *(float2*)&g_node_h[o * HH + col] = h;
                            *(float2*)&g_node_c[o * HH + col] = c;
                        }
                    }
                } else {
#pragma unroll
                    for (int s = 0; s < 4; s++) {
                        int r = ng * 4 + s;
                        int idx = C->idx[r];
                        if (idx < 0) continue;
#pragma unroll
                        for (int p = 0; p < 2; p++) {
                            int col = jt * 32 + jg * 4 + p * 2;
#pragma unroll
                            for (int gg2 = 0; gg2 < 5; gg2++) {
                                float2 v = upk(acc[s][p][gg2]);
                                int bi2 = (idx * FIVE_H + gg2 * HH + col) * PS + split;
                                g_part[bi2] = v.x;
                                g_part[bi2 + PS] = v.y;
                            }
                        }
                    }
                }
                __syncthreads();
            }
            grid_barrier(nblk);

            if (sv > 1) {
                for (int f = blockIdx.x * 256 + tid; f < M * HH; f += nblk * 256) {
                    int j = f & 511, i = f >> 9;
                    int item = g_items[start + i];
                    int b = item >> 7, n = item & 127;
                    int2 ch = g_ch[b * NN + n];
                    float ga[5];
#pragma unroll
                    for (int gg2 = 0; gg2 < 5; gg2++) {
                        int bb2 = (i * FIVE_H + gg2 * HH + j) * PS;
                        float s = 0.f;
                        for (int t = 0; t < sv; t++) s += g_part[bb2 + t];
                        ga[gg2] = s + rb[gg2 * HH + j];
                    }
                    float cl = csrc(b, ch.x)[j];
                    float cr = csrc(b, ch.y)[j];
                    float c = sigf(ga[1]) * cl + sigf(ga[2]) * cr + sigf(ga[0]) * tanhf(ga[4]);
                    float h = sigf(ga[3]) * tanhf(c);
                    int o = b * NN + n;
                    g_node_h[o * HH + j] = h;
                    g_node_c[o * HH + j] = c;
                }
                grid_barrier(nblk);
            }
        }
    }
}

// ------------------------- final readout ------------------------------------
__global__ void final_kernel(float* __restrict__ out)
{
    int idx = blockIdx.x * blockDim.x + threadIdx.x;
    if (idx >= BB * HH) return;
    int b = idx >> 9;
    int j = idx & 511;
    int root = g_fin[b] - 128;
    out[idx] = g_node_h[(b * NN + root) * HH + j];
}

// ------------------------- launch -------------------------------------------
extern "C" void kernel_launch(void* const* d_in, const int* in_sizes, int n_in,
                              void* d_out, int out_size)
{
    const float* sentence    = (const float*)d_in[0];
    const int*   transitions = (const int*)  d_in[1];
    const float* word_W      = (const float*)d_in[2];
    const float* word_b      = (const float*)d_in[3];
    const float* bn_gamma    = (const float*)d_in[4];
    const float* bn_beta     = (const float*)d_in[5];
    const float* reduce_W    = (const float*)d_in[6];
    const float* reduce_b    = (const float*)d_in[7];
    float* out = (float*)d_out;

    int dev = 0, nsm = 148;
    cudaGetDevice(&dev);
    cudaDeviceGetAttribute(&nsm, cudaDevAttrMultiProcessorCount, dev);
    cudaFuncSetAttribute(scan_kernel, cudaFuncAttributeMaxDynamicSharedMemorySize, SMEM_SZ);

    word_gemm<<<dim3(TWO_H / 64, NLE / 128), 256>>>(sentence, word_W, word_b);
    zero_stats<<<4, 256>>>();
    bn_stats<<<dim3(4, 256), 256>>>();
    bn_finalize<<<4, 256>>>(bn_gamma, bn_beta);
    bn_apply<<<(NLE * TWO_H) / 256, 256>>>();

    wprep<<<(TWO_H * FIVE_H + 255) / 256, 256>>>(reduce_W);
    meta_kernel<<<1, 128>>>(transitions);

    scan_kernel<<<nsm, 256, SMEM_SZ>>>(reduce_W, reduce_b, nsm);

    final_kernel<<<(BB * HH + 255) / 256, 256>>>(out);
}

// round 10
// speedup vs baseline: 3.0718x; 1.0741x over previous
#include <cuda_runtime.h>
#include <cuda_bf16.h>
#include <math.h>

typedef unsigned long long ull;
typedef unsigned int uint;

// ---------------------------------------------------------------------------
// SPINN TreeLSTM: level-scheduled tree evaluation.
//   Big levels (M>128): mma.sync bf16x3 (fp32-faithful) tensor path, ldmatrix.
//   Small levels:       FFMA2 split-K SIMT path.
// Launch order arranged so scan_kernel is launch #4 (ncu capture slot).
// ---------------------------------------------------------------------------

#define BB 128
#define LL 128
#define EE 512
#define HH 512
#define TT 255
#define NN 127
#define TWO_H 1024
#define FIVE_H 2560
#define NLE (BB*LL)
#define PS 8

// dynamic smem layout (16B-aligned base):
//   two chunk buffers of 40960B: [AH 10240 | AL 10240 | BH 10240 | BL 10240]
//   (A/B tiles are 128 rows x 40 bf16, stride 80B)
#define GBUF   40960
#define A_LO   10240
#define B_HI   20480
#define B_LO   30720
#define CTRL_OFF 81920
#define SMEM_SZ  90112

struct Ctrl {
    const float* hl[128];
    const float* hr[128];
    const float* cl[128];
    const float* cr[128];
    int  out[128];
    int  idx[128];
};

// ------------------------- scratch (static device memory) ------------------
__device__ float g_tmp[NLE * TWO_H];
__device__ float g_hbuf[BB * LL * HH];
__device__ float g_cbuf[BB * LL * HH];
__device__ float g_node_h[BB * NN * HH];
__device__ float g_node_c[BB * NN * HH];
__device__ float g_gates[8192 * FIVE_H];           // tensor-path gate preacts
__device__ float g_part[128 * FIVE_H * PS];        // small-path split-K partials
__device__ __nv_bfloat16 g_wb_hi[FIVE_H * TWO_H];  // W bf16 hi, [n][k]
__device__ __nv_bfloat16 g_wb_lo[FIVE_H * TWO_H];  // W bf16 lo, [n][k]
__device__ __nv_bfloat16 g_xa_hi[8192 * TWO_H];    // level x bf16 hi, [idx][k]
__device__ __nv_bfloat16 g_xa_lo[8192 * TWO_H];    // level x bf16 lo
__device__ float g_sum[TWO_H];
__device__ float g_sumsq[TWO_H];
__device__ int2  g_ch[BB * NN];
__device__ int   g_items[BB * NN];
__device__ int   g_lv_start[132];
__device__ int   g_maxlvl;
__device__ int   g_fin[BB];
__device__ int            g_bar_count;
__device__ volatile int   g_bar_gen;

__device__ __forceinline__ float sigf(float x) { return 1.0f / (1.0f + expf(-x)); }

__device__ __forceinline__ ull ffma2(ull x, ull w, ull a) {
    asm("fma.rn.f32x2 %0, %1, %2, %0;" : "+l"(a) : "l"(x), "l"(w));
    return a;
}
__device__ __forceinline__ ull pk2(float v) {
    ull r; asm("mov.b64 %0, {%1, %2};" : "=l"(r) : "f"(v), "f"(v)); return r;
}
__device__ __forceinline__ float2 upk(ull v) {
    float2 f; asm("mov.b64 {%0, %1}, %2;" : "=f"(f.x), "=f"(f.y) : "l"(v)); return f;
}
__device__ __forceinline__ uint s2u(const void* p) {
    uint a; asm("{ .reg .u64 t; cvta.to.shared.u64 t, %1; cvt.u32.u64 %0, t; }"
                : "=r"(a) : "l"(p));
    return a;
}

// mma.sync m16n8k16 row.col f32.bf16.bf16.f32 (base-target HMMA)
__device__ __forceinline__ void mma_bf16(float* c, uint a0, uint a1, uint a2, uint a3,
                                         uint b0, uint b1) {
    asm volatile("mma.sync.aligned.m16n8k16.row.col.f32.bf16.bf16.f32 "
                 "{%0,%1,%2,%3}, {%4,%5,%6,%7}, {%8,%9}, {%0,%1,%2,%3};"
                 : "+f"(c[0]), "+f"(c[1]), "+f"(c[2]), "+f"(c[3])
                 : "r"(a0), "r"(a1), "r"(a2), "r"(a3), "r"(b0), "r"(b1));
}

#define LDSM4(r0, r1, r2, r3, addr) asm volatile( \
    "ldmatrix.sync.aligned.m8n8.x4.shared.b16 {%0,%1,%2,%3}, [%4];" \
    : "=r"(r0), "=r"(r1), "=r"(r2), "=r"(r3) : "r"(addr))

__device__ __forceinline__ void cvt2(float a, float b, uint &hp, uint &lp) {
    __nv_bfloat16 ha = __float2bfloat16(a), hb = __float2bfloat16(b);
    float ra = a - __bfloat162float(ha);
    float rb2 = b - __bfloat162float(hb);
    __nv_bfloat16 la = __float2bfloat16(ra), lb = __float2bfloat16(rb2);
    hp = (uint)*(unsigned short*)&ha | ((uint)*(unsigned short*)&hb << 16);
    lp = (uint)*(unsigned short*)&la | ((uint)*(unsigned short*)&lb << 16);
}

__device__ __forceinline__ const float* hsrc(int b, int id) {
    return (id < 128) ? (g_hbuf + (b * LL + id) * HH)
                      : (g_node_h + (b * NN + (id - 128)) * HH);
}
__device__ __forceinline__ const float* csrc(int b, int id) {
    return (id < 128) ? (g_cbuf + (b * LL + id) * HH)
                      : (g_node_c + (b * NN + (id - 128)) * HH);
}

__device__ __forceinline__ void grid_barrier(int nblk) {
    __syncthreads();
    if (threadIdx.x == 0) {
        __threadfence();
        int gen = g_bar_gen;
        if (atomicAdd(&g_bar_count, 1) == nblk - 1) {
            g_bar_count = 0;
            __threadfence();
            g_bar_gen = gen + 1;
        } else {
            while (g_bar_gen == gen) { __nanosleep(32); }
        }
        __threadfence();
    }
    __syncthreads();
}

// ------------------- launch #1: word GEMM (f32x2) + stat zeroing ------------
__global__ __launch_bounds__(256) void word_gemm(
    const float* __restrict__ A, const float* __restrict__ Wm,
    const float* __restrict__ bias)
{
    __shared__ float As[32 * 129];
    __shared__ __align__(16) float Bs[32][64];
    const int tid = threadIdx.x;
    const int tx = tid & 15;
    const int ty = tid >> 4;
    const int rowBase = blockIdx.y * 128;
    const int colBase = blockIdx.x * 64;

    if (blockIdx.x == 0 && blockIdx.y == 0) {
        for (int i = tid; i < TWO_H; i += 256) { g_sum[i] = 0.f; g_sumsq[i] = 0.f; }
    }

    ull acc[8][2];
#pragma unroll
    for (int i = 0; i < 8; i++) { acc[i][0] = 0ull; acc[i][1] = 0ull; }

    for (int k0 = 0; k0 < EE; k0 += 32) {
#pragma unroll
        for (int i = 0; i < 4; i++) {
            int f = tid + i * 256;
            int r = f >> 3, c4 = f & 7;
            float4 v = *(const float4*)(A + (rowBase + r) * EE + k0 + c4 * 4);
            As[(c4 * 4 + 0) * 129 + r] = v.x;
            As[(c4 * 4 + 1) * 129 + r] = v.y;
            As[(c4 * 4 + 2) * 129 + r] = v.z;
            As[(c4 * 4 + 3) * 129 + r] = v.w;
        }
#pragma unroll
        for (int i = 0; i < 2; i++) {
            int f = tid + i * 256;
            int r = f >> 4, c4 = f & 15;
            *(float4*)&Bs[r][c4 * 4] =
                *(const float4*)(Wm + (k0 + r) * TWO_H + colBase + c4 * 4);
        }
        __syncthreads();
#pragma unroll 8
        for (int kk = 0; kk < 32; kk++) {
            const float* ar = As + kk * 129 + ty * 8;
            ulonglong2 w2 = *(const ulonglong2*)&Bs[kk][tx * 4];
#pragma unroll
            for (int i = 0; i < 8; i++) {
                ull xp = pk2(ar[i]);
                acc[i][0] = ffma2(xp, w2.x, acc[i][0]);
                acc[i][1] = ffma2(xp, w2.y, acc[i][1]);
            }
        }
        __syncthreads();
    }

    const int col = colBase + tx * 4;
    float2 b0 = *(const float2*)(bias + col);
    float2 b1 = *(const float2*)(bias + col + 2);
#pragma unroll
    for (int i = 0; i < 8; i++) {
        int row = rowBase + ty * 8 + i;
        float2 v0 = upk(acc[i][0]);
        float2 v1 = upk(acc[i][1]);
        v0.x += b0.x; v0.y += b0.y;
        v1.x += b1.x; v1.y += b1.y;
        *(float2*)&g_tmp[row * TWO_H + col] = v0;
        *(float2*)&g_tmp[row * TWO_H + col + 2] = v1;
    }
}

// ----- launch #2: fused bn_stats (blocks 0..1023) + wprep (1024..11263) -----
// ----- + meta tree build (block 11264)                                  -----
__global__ __launch_bounds__(256) void stats_wprep_meta(
    const float* __restrict__ W, const int* __restrict__ trans)
{
    __shared__ int cnt[132];
    __shared__ int cur[132];
    __shared__ int smax;
    const int bx = blockIdx.x;
    const int tid = threadIdx.x;

    if (bx < 1024) {
        // ---- bn stats ----
        int ch = (bx & 3) * 256 + tid;
        int rowBase = (bx >> 2) * 64;
        float s = 0.f, q = 0.f;
#pragma unroll 4
        for (int r = 0; r < 64; r++) {
            float v = g_tmp[(rowBase + r) * TWO_H + ch];
            s += v; q += v * v;
        }
        atomicAdd(&g_sum[ch], s);
        atomicAdd(&g_sumsq[ch], q);
    } else if (bx < 11264) {
        // ---- W split to bf16 hi/lo, [n][k] ----
        int f = (bx - 1024) * 256 + tid;       // f = k*2560 + n
        if (f < TWO_H * FIVE_H) {
            int k = f / FIVE_H, n = f - k * FIVE_H;
            float w = W[f];
            __nv_bfloat16 hb = __float2bfloat16(w);
            float rest = w - __bfloat162float(hb);
            __nv_bfloat16 lb = __float2bfloat16(rest);
            g_wb_hi[n * TWO_H + k] = hb;
            g_wb_lo[n * TWO_H + k] = lb;
        }
    } else {
        // ---- metadata: per-row shift-reduce tree + level buckets ----
        int b = tid;
        for (int i = b; i < 132; i += 256) cnt[i] = 0;
        if (b == 0) smax = 0;
        __syncthreads();
        if (b < 128) {
            int sid[130];
            int slv[130];
            int nlv[NN];
            int ptr = 0, bp = 0, n = 0;
            for (int t = 0; t < TT; t++) {
                int act = trans[b * TT + t];
                if (act == 2) {
                    sid[ptr] = bp; slv[ptr] = 0; ptr++; bp++;
                } else if (act == 3) {
                    int lv = max(slv[ptr - 2], slv[ptr - 1]) + 1;
                    g_ch[b * NN + n] = make_int2(sid[ptr - 2], sid[ptr - 1]);
                    nlv[n] = lv;
                    sid[ptr - 2] = 128 + n; slv[ptr - 2] = lv;
                    ptr--; n++;
                }
            }
            g_fin[b] = sid[0];
            int mymax = 0;
            for (int i = 0; i < n; i++) {
                atomicAdd(&cnt[nlv[i]], 1);
                mymax = max(mymax, nlv[i]);
            }
            atomicMax(&smax, mymax);
            __syncthreads();
            if (b == 0) {
                int a = 0;
                for (int lv = 0; lv <= 130; lv++) {
                    cur[lv] = a;
                    g_lv_start[lv] = a;
                    a += cnt[lv];
                }
                g_lv_start[131] = a;
                g_maxlvl = smax;
            }
            __syncthreads();
            for (int i = 0; i < n; i++) {
                int idx = atomicAdd(&cur[nlv[i]], 1);
                g_items[idx] = (b << 7) | i;
            }
        } else {
            __syncthreads();
            __syncthreads();
        }
    }
}

// ------- launch #3: bn apply with inline finalize (16 rows / thread) --------
__global__ __launch_bounds__(256) void bn_apply_fin(
    const float* __restrict__ gamma, const float* __restrict__ beta)
{
    int id = blockIdx.x * 256 + threadIdx.x;       // < 1024*1024
    int ch = id & 1023;
    int rb2 = id >> 10;                            // row block, 16 rows each
    const float invN = 1.0f / (float)NLE;
    float mean = g_sum[ch] * invN;
    float var  = g_sumsq[ch] * invN - mean * mean;
    float sc   = gamma[ch] * rsqrtf(var + 1e-5f);
    float sh   = beta[ch] - mean * sc;
#pragma unroll 4
    for (int rr = 0; rr < 16; rr++) {
        int row = rb2 * 16 + rr;
        float v = g_tmp[row * TWO_H + ch] * sc + sh;
        if (ch < HH) g_hbuf[row * HH + ch] = v;
        else         g_cbuf[row * HH + (ch - HH)] = v;
    }
}

// ------------------- launch #4: persistent level-scan kernel ----------------
extern __shared__ char dsm_raw[];

__global__ __launch_bounds__(256) void scan_kernel(
    const float* __restrict__ W, const float* __restrict__ rb, int nblk)
{
    const int tid = threadIdx.x;
    const int lane = tid & 31;
    const int wid = tid >> 5;
    const int wm = wid >> 1;           // 0..3 : warp m-block (32 rows)
    const int wn = wid & 1;            // 0..1 : warp n-block (64 cols)
    const int g = lane >> 2;           // fragment group row
    const int tig = lane & 3;          // thread-in-group

    char* base = dsm_raw;
    Ctrl* C = (Ctrl*)(base + CTRL_OFF);
    float* Xs = (float*)(base);            // small path: 16.5KB (aliases buffers)
    float* Ws = (float*)(base + 16896);    // small path: 20KB

    // ldmatrix per-thread address bases (constant; depend on lane/warp only)
    const int jmat = lane >> 3, jr = lane & 7;
    uint aBase[2], bBase[4];
    {
        uint s0 = s2u(base);
#pragma unroll
        for (int mf = 0; mf < 2; mf++)
            aBase[mf] = s0 + (uint)((wm * 32 + mf * 16 + (jmat & 1) * 8 + jr) * 80
                                    + (jmat >> 1) * 16);
#pragma unroll
        for (int p = 0; p < 4; p++)
            bBase[p] = s0 + B_HI + (uint)((wn * 64 + (2 * p + (jmat >> 1)) * 8 + jr) * 80
                                          + (jmat & 1) * 16);
    }

    const int maxlvl = g_maxlvl;

    for (int lv = 1; lv <= maxlvl; lv++) {
        const int start = g_lv_start[lv];
        const int M = g_lv_start[lv + 1] - start;
        if (M <= 0) { grid_barrier(nblk); continue; }

        if (M > 128) {
            // ======== tensor path: per-level x -> bf16 hi/lo conversion =====
            int totalc = M * 64;                 // 16 elems per work item
            for (int u = blockIdx.x * 256 + tid; u < totalc; u += nblk * 256) {
                int i = u >> 6;
                int kq = (u & 63) << 4;
                int item = g_items[start + i];
                int b = item >> 7, n = item & 127;
                int2 ch = g_ch[b * NN + n];
                const float* src = (kq < HH) ? (hsrc(b, ch.x) + kq)
                                             : (hsrc(b, ch.y) + kq - HH);
                char* dh = (char*)(g_xa_hi + i * TWO_H + kq);
                char* dl = (char*)(g_xa_lo + i * TWO_H + kq);
#pragma unroll
                for (int q = 0; q < 4; q++) {
                    float4 v = *(const float4*)(src + q * 4);
                    uint h0, h1, l0, l1;
                    cvt2(v.x, v.y, h0, l0);
                    cvt2(v.z, v.w, h1, l1);
                    *(uint2*)(dh + q * 8) = make_uint2(h0, h1);
                    *(uint2*)(dl + q * 8) = make_uint2(l0, l1);
                }
            }
            grid_barrier(nblk);

            // ======== mma units: 128m x 128n tiles, K=1024 in 32-chunks =====
            const int mtiles = (M + 127) >> 7;
            const int units = mtiles * 20;
            const int r2 = tid >> 1, hf = tid & 1;      // staging coords
            for (int u = blockIdx.x; u < units; u += nblk) {
                const int mt = u / 20;
                const int nt = u - mt * 20;

                // stage chunk 0 into buffer 0
                {
                    char* bp = base;
                    const char* sa_h = (const char*)(g_xa_hi + (mt * 128 + r2) * TWO_H + hf * 16);
                    const char* sa_l = (const char*)(g_xa_lo + (mt * 128 + r2) * TWO_H + hf * 16);
                    const char* sb_h = (const char*)(g_wb_hi + (nt * 128 + r2) * TWO_H + hf * 16);
                    const char* sb_l = (const char*)(g_wb_lo + (nt * 128 + r2) * TWO_H + hf * 16);
                    int d = r2 * 80 + hf * 32;
                    *(uint4*)(bp + d)               = *(const uint4*)(sa_h);
                    *(uint4*)(bp + d + 16)          = *(const uint4*)(sa_h + 16);
                    *(uint4*)(bp + A_LO + d)        = *(const uint4*)(sa_l);
                    *(uint4*)(bp + A_LO + d + 16)   = *(const uint4*)(sa_l + 16);
                    *(uint4*)(bp + B_HI + d)        = *(const uint4*)(sb_h);
                    *(uint4*)(bp + B_HI + d + 16)   = *(const uint4*)(sb_h + 16);
                    *(uint4*)(bp + B_LO + d)        = *(const uint4*)(sb_l);
                    *(uint4*)(bp + B_LO + d + 16)   = *(const uint4*)(sb_l + 16);
                }
                __syncthreads();

                float acc[2][8][4];
#pragma unroll
                for (int mf = 0; mf < 2; mf++)
#pragma unroll
                    for (int nf = 0; nf < 8; nf++)
#pragma unroll
                        for (int q = 0; q < 4; q++) acc[mf][nf][q] = 0.f;

                for (int chk = 0; chk < 32; chk++) {
                    const uint bufo = (uint)(chk & 1) * GBUF;
                    char* nxt = base + ((chk + 1) & 1) * GBUF;

                    // prefetch next chunk (LDG latency hidden by mma below)
                    uint4 pa[4], pb[4];
                    if (chk < 31) {
                        int ko = (chk + 1) * 32 + hf * 16;
                        const char* sa_h = (const char*)(g_xa_hi + (mt * 128 + r2) * TWO_H + ko);
                        const char* sa_l = (const char*)(g_xa_lo + (mt * 128 + r2) * TWO_H + ko);
                        const char* sb_h = (const char*)(g_wb_hi + (nt * 128 + r2) * TWO_H + ko);
                        const char* sb_l = (const char*)(g_wb_lo + (nt * 128 + r2) * TWO_H + ko);
                        pa[0] = *(const uint4*)(sa_h);     pa[1] = *(const uint4*)(sa_h + 16);
                        pa[2] = *(const uint4*)(sa_l);     pa[3] = *(const uint4*)(sa_l + 16);
                        pb[0] = *(const uint4*)(sb_h);     pb[1] = *(const uint4*)(sb_h + 16);
                        pb[2] = *(const uint4*)(sb_l);     pb[3] = *(const uint4*)(sb_l + 16);
                    }

                    // compute on current buffer via ldmatrix fragments
#pragma unroll
                    for (int half = 0; half < 2; half++) {
                        const uint kb = bufo + (uint)half * 32;
                        uint bh[8][2], bl[8][2];
#pragma unroll
                        for (int p = 0; p < 4; p++) {
                            LDSM4(bh[2 * p][0], bh[2 * p][1],
                                  bh[2 * p + 1][0], bh[2 * p + 1][1], bBase[p] + kb);
                            LDSM4(bl[2 * p][0], bl[2 * p][1],
                                  bl[2 * p + 1][0], bl[2 * p + 1][1],
                                  bBase[p] + kb + (B_LO - B_HI));
                        }
#pragma unroll
                        for (int mf = 0; mf < 2; mf++) {
                            uint a0, a1, a2, a3, l0, l1, l2, l3;
                            LDSM4(a0, a1, a2, a3, aBase[mf] + kb);
                            LDSM4(l0, l1, l2, l3, aBase[mf] + kb + A_LO);
#pragma unroll
                            for (int nf = 0; nf < 8; nf++) {
                                mma_bf16(acc[mf][nf], a0, a1, a2, a3, bh[nf][0], bh[nf][1]);
                                mma_bf16(acc[mf][nf], l0, l1, l2, l3, bh[nf][0], bh[nf][1]);
                                mma_bf16(acc[mf][nf], a0, a1, a2, a3, bl[nf][0], bl[nf][1]);
                            }
                        }
                    }

                    if (chk < 31) {
                        int d = r2 * 80 + hf * 32;
                        *(uint4*)(nxt + d)             = pa[0];
                        *(uint4*)(nxt + d + 16)        = pa[1];
                        *(uint4*)(nxt + A_LO + d)      = pa[2];
                        *(uint4*)(nxt + A_LO + d + 16) = pa[3];
                        *(uint4*)(nxt + B_HI + d)      = pb[0];
                        *(uint4*)(nxt + B_HI + d + 16) = pb[1];
                        *(uint4*)(nxt + B_LO + d)      = pb[2];
                        *(uint4*)(nxt + B_LO + d + 16) = pb[3];
                    }
                    __syncthreads();
                }

                // write accumulators to gate buffer
#pragma unroll
                for (int mf = 0; mf < 2; mf++) {
                    int row = wm * 32 + mf * 16 + g;
                    int gi = mt * 128 + row;
                    float* dst0 = g_gates + (size_t)gi * FIVE_H;
#pragma unroll
                    for (int nf = 0; nf < 8; nf++) {
                        int col = nt * 128 + wn * 64 + nf * 8 + 2 * tig;
                        *(float2*)(dst0 + col) =
                            make_float2(acc[mf][nf][0], acc[mf][nf][1]);
                        *(float2*)(dst0 + 8 * FIVE_H + col) =
                            make_float2(acc[mf][nf][2], acc[mf][nf][3]);
                    }
                }
            }
            grid_barrier(nblk);

            // epilogue: bias + TreeLSTM from g_gates
            for (int f = blockIdx.x * 256 + tid; f < M * HH; f += nblk * 256) {
                int j = f & 511, i = f >> 9;
                int item = g_items[start + i];
                int b = item >> 7, n = item & 127;
                int2 ch = g_ch[b * NN + n];
                const float* gg = g_gates + (size_t)i * FIVE_H;
                float ai  = gg[0 * HH + j] + rb[0 * HH + j];
                float afl = gg[1 * HH + j] + rb[1 * HH + j];
                float afr = gg[2 * HH + j] + rb[2 * HH + j];
                float ao  = gg[3 * HH + j] + rb[3 * HH + j];
                float ag  = gg[4 * HH + j] + rb[4 * HH + j];
                float cl = csrc(b, ch.x)[j];
                float cr = csrc(b, ch.y)[j];
                float c = sigf(afl) * cl + sigf(afr) * cr + sigf(ai) * tanhf(ag);
                float h = sigf(ao) * tanhf(c);
                int o = b * NN + n;
                g_node_h[o * HH + j] = h;
                g_node_c[o * HH + j] = c;
            }
            grid_barrier(nblk);
        } else {
            // ================= small path: FFMA2 split-K ====================
            const int base_tiles = 16;
            int sv = 1;
            while (sv < PS && base_tiles * (sv << 1) <= nblk) sv <<= 1;
            const int cpu = 32 / sv;
            const int units = base_tiles * sv;
            const int ng = tid >> 3, jg = tid & 7;

            for (int u = blockIdx.x; u < units; u += nblk) {
                const int tile = u % base_tiles;
                const int split = u / base_tiles;
                const int jt = tile & 15;
                const int c0 = split * cpu, c1 = c0 + cpu;

                if (tid < 128) {
                    int gi = start + tid;
                    bool valid = gi < start + M;
                    int item = g_items[valid ? gi : start];
                    int b = item >> 7, n = item & 127;
                    int2 ch = g_ch[b * NN + n];
                    C->hl[tid] = hsrc(b, ch.x);
                    C->hr[tid] = hsrc(b, ch.y);
                    C->cl[tid] = csrc(b, ch.x);
                    C->cr[tid] = csrc(b, ch.y);
                    C->out[tid] = valid ? (b * NN + n) : -1;
                    C->idx[tid] = valid ? tid : -1;
                }
                __syncthreads();

                ull acc[4][2][5];
#pragma unroll
                for (int s = 0; s < 4; s++)
#pragma unroll
                    for (int p = 0; p < 2; p++)
#pragma unroll
                        for (int gg2 = 0; gg2 < 5; gg2++) acc[s][p][gg2] = 0ull;

                float4 xr[4];
                float4 wr[5];
                {
                    const int kc0 = c0 * 32;
                    const bool left = kc0 < HH;
                    const int koff = left ? kc0 : (kc0 - HH);
#pragma unroll
                    for (int i = 0; i < 4; i++) {
                        int f = tid + i * 256;
                        int r = f >> 3, c4 = f & 7;
                        const float* bp2 = (left ? C->hl[r] : C->hr[r]) + koff;
                        xr[i] = *(const float4*)(bp2 + c4 * 4);
                    }
#pragma unroll
                    for (int i = 0; i < 5; i++) {
                        int f4 = tid + i * 256;
                        int c4 = f4 & 7, gg2 = (f4 >> 3) % 5, k = f4 / 40;
                        wr[i] = *(const float4*)(W + (kc0 + k) * FIVE_H + gg2 * HH + jt * 32 + c4 * 4);
                    }
                }

                for (int chk = c0; chk < c1; chk++) {
#pragma unroll
                    for (int i = 0; i < 4; i++) {
                        int f = tid + i * 256;
                        int r = f >> 3, c4 = f & 7;
                        Xs[(c4 * 4 + 0) * 129 + r] = xr[i].x;
                        Xs[(c4 * 4 + 1) * 129 + r] = xr[i].y;
                        Xs[(c4 * 4 + 2) * 129 + r] = xr[i].z;
                        Xs[(c4 * 4 + 3) * 129 + r] = xr[i].w;
                    }
#pragma unroll
                    for (int i = 0; i < 5; i++)
                        *(float4*)&Ws[(tid + i * 256) * 4] = wr[i];
                    __syncthreads();

                    if (chk + 1 < c1) {
                        const int kc0 = (chk + 1) * 32;
                        const bool left = kc0 < HH;
                        const int koff = left ? kc0 : (kc0 - HH);
#pragma unroll
                        for (int i = 0; i < 4; i++) {
                            int f = tid + i * 256;
                            int r = f >> 3, c4 = f & 7;
                            const float* bp2 = (left ? C->hl[r] : C->hr[r]) + koff;
                            xr[i] = *(const float4*)(bp2 + c4 * 4);
                        }
#pragma unroll
                        for (int i = 0; i < 5; i++) {
                            int f4 = tid + i * 256;
                            int c4 = f4 & 7, gg2 = (f4 >> 3) % 5, k = f4 / 40;
                            wr[i] = *(const float4*)(W + (kc0 + k) * FIVE_H + gg2 * HH + jt * 32 + c4 * 4);
                        }
                    }

#pragma unroll 8
                    for (int k = 0; k < 32; k++) {
                        const float* xrow = Xs + k * 129 + ng * 4;
                        ull xp0 = pk2(xrow[0]);
                        ull xp1 = pk2(xrow[1]);
                        ull xp2 = pk2(xrow[2]);
                        ull xp3 = pk2(xrow[3]);
#pragma unroll
                        for (int gg2 = 0; gg2 < 5; gg2++) {
                            ulonglong2 w = *(const ulonglong2*)&Ws[(k * 5 + gg2) * 32 + jg * 4];
                            acc[0][0][gg2] = ffma2(xp0, w.x, acc[0][0][gg2]);
                            acc[0][1][gg2] = ffma2(xp0, w.y, acc[0][1][gg2]);
                            acc[1][0][gg2] = ffma2(xp1, w.x, acc[1][0][gg2]);
                            acc[1][1][gg2] = ffma2(xp1, w.y, acc[1][1][gg2]);
                            acc[2][0][gg2] = ffma2(xp2, w.x, acc[2][0][gg2]);
                            acc[2][1][gg2] = ffma2(xp2, w.y, acc[2][1][gg2]);
                            acc[3][0][gg2] = ffma2(xp3, w.x, acc[3][0][gg2]);
                            acc[3][1][gg2] = ffma2(xp3, w.y, acc[3][1][gg2]);
                        }
                    }
                    __syncthreads();
                }

                if (sv == 1) {
#pragma unroll
                    for (int s = 0; s < 4; s++) {
                        int r = ng * 4 + s;
                        int o = C->out[r];
                        if (o < 0) continue;
                        const float* clp = C->cl[r];
                        const float* crp = C->cr[r];
#pragma unroll
                        for (int p = 0; p < 2; p++) {
                            int col = jt * 32 + jg * 4 + p * 2;
                            float2 vi  = upk(acc[s][p][0]);
                            float2 vfl = upk(acc[s][p][1]);
                            float2 vfr = upk(acc[s][p][2]);
                            float2 vo  = upk(acc[s][p][3]);
                            float2 vg  = upk(acc[s][p][4]);
                            float2 bi  = *(const float2*)(rb + 0 * HH + col);
                            float2 bfl = *(const float2*)(rb + 1 * HH + col);
                            float2 bfr = *(const float2*)(rb + 2 * HH + col);
                            float2 bo  = *(const float2*)(rb + 3 * HH + col);
                            float2 bg  = *(const float2*)(rb + 4 * HH + col);
                            float2 cl = *(const float2*)(clp + col);
                            float2 cr = *(const float2*)(crp + col);
                            float2 c, h;
                            c.x = sigf(vfl.x + bfl.x) * cl.x + sigf(vfr.x + bfr.x) * cr.x
                                + sigf(vi.x + bi.x) * tanhf(vg.x + bg.x);
                            c.y = sigf(vfl.y + bfl.y) * cl.y + sigf(vfr.y + bfr.y) * cr.y
                                + sigf(vi.y + bi.y) * tanhf(vg.y + bg.y);
                            h.x = sigf(vo.x + bo.x) * tanhf(c.x);
                            h.y = sigf(vo.y + bo.y) * tanhf(c.y);
                            *(float2*)&g_node_h[o * HH + col] = h;
                            *(float2*)&g_node_c[o * HH + col] = c;
                        }
                    }
                } else {
#pragma unroll
                    for (int s = 0; s < 4; s++) {
                        int r = ng * 4 + s;
                        int idx = C->idx[r];
                        if (idx < 0) continue;
#pragma unroll
                        for (int p = 0; p < 2; p++) {
                            int col = jt * 32 + jg * 4 + p * 2;
#pragma unroll
                            for (int gg2 = 0; gg2 < 5; gg2++) {
                                float2 v = upk(acc[s][p][gg2]);
                                int bi2 = (idx * FIVE_H + gg2 * HH + col) * PS + split;
                                g_part[bi2] = v.x;
                                g_part[bi2 + PS] = v.y;
                            }
                        }
                    }
                }
                __syncthreads();
            }
            grid_barrier(nblk);

            if (sv > 1) {
                for (int f = blockIdx.x * 256 + tid; f < M * HH; f += nblk * 256) {
                    int j = f & 511, i = f >> 9;
                    int item = g_items[start + i];
                    int b = item >> 7, n = item & 127;
                    int2 ch = g_ch[b * NN + n];
                    float ga[5];
#pragma unroll
                    for (int gg2 = 0; gg2 < 5; gg2++) {
                        int bb2 = (i * FIVE_H + gg2 * HH + j) * PS;
                        float s = 0.f;
                        for (int t = 0; t < sv; t++) s += g_part[bb2 + t];
                        ga[gg2] = s + rb[gg2 * HH + j];
                    }
                    float cl = csrc(b, ch.x)[j];
                    float cr = csrc(b, ch.y)[j];
                    float c = sigf(ga[1]) * cl + sigf(ga[2]) * cr + sigf(ga[0]) * tanhf(ga[4]);
                    float h = sigf(ga[3]) * tanhf(c);
                    int o = b * NN + n;
                    g_node_h[o * HH + j] = h;
                    g_node_c[o * HH + j] = c;
                }
                grid_barrier(nblk);
            }
        }
    }
}

// ------------------------- launch #5: final readout --------------------------
__global__ void final_kernel(float* __restrict__ out)
{
    int idx = blockIdx.x * blockDim.x + threadIdx.x;
    if (idx >= BB * HH) return;
    int b = idx >> 9;
    int j = idx & 511;
    int root = g_fin[b] - 128;
    out[idx] = g_node_h[(b * NN + root) * HH + j];
}

// ------------------------- launch -------------------------------------------
extern "C" void kernel_launch(void* const* d_in, const int* in_sizes, int n_in,
                              void* d_out, int out_size)
{
    const float* sentence    = (const float*)d_in[0];
    const int*   transitions = (const int*)  d_in[1];
    const float* word_W      = (const float*)d_in[2];
    const float* word_b      = (const float*)d_in[3];
    const float* bn_gamma    = (const float*)d_in[4];
    const float* bn_beta     = (const float*)d_in[5];
    const float* reduce_W    = (const float*)d_in[6];
    const float* reduce_b    = (const float*)d_in[7];
    float* out = (float*)d_out;

    int dev = 0, nsm = 148;
    cudaGetDevice(&dev);
    cudaDeviceGetAttribute(&nsm, cudaDevAttrMultiProcessorCount, dev);
    cudaFuncSetAttribute(scan_kernel, cudaFuncAttributeMaxDynamicSharedMemorySize, SMEM_SZ);

    // #1
    word_gemm<<<dim3(TWO_H / 64, NLE / 128), 256>>>(sentence, word_W, word_b);
    // #2 : bn_stats (1024) + wprep (10240) + meta (1)
    stats_wprep_meta<<<11265, 256>>>(reduce_W, transitions);
    // #3
    bn_apply_fin<<<4096, 256>>>(bn_gamma, bn_beta);
    // #4 : the kernel we want ncu to capture
    scan_kernel<<<nsm, 256, SMEM_SZ>>>(reduce_W, reduce_b, nsm);
    // #5
    final_kernel<<<(BB * HH + 255) / 256, 256>>>(out);
}

// round 12
// speedup vs baseline: 3.3091x; 1.0772x over previous
#include <cuda_runtime.h>
#include <cuda_bf16.h>
#include <math.h>

typedef unsigned long long ull;
typedef unsigned int uint;

// ---------------------------------------------------------------------------
// SPINN TreeLSTM: level-scheduled tree evaluation.
//   Big levels (M>128): mma.sync bf16x3, ldmatrix, 3-stage cp.async pipeline,
//                       split-K for mid-size levels.
//   Small levels:       FFMA2 split-K SIMT path.
// Launch order keeps scan_kernel as launch #4 (ncu capture slot).
// R12 fix: SMEM_SZ was 126976 with Ctrl (5120B) at 122880 -> smem OOB. Now 131072.
// ---------------------------------------------------------------------------

#define BB 128
#define LL 128
#define EE 512
#define HH 512
#define TT 255
#define NN 127
#define TWO_H 1024
#define FIVE_H 2560
#define NLE (BB*LL)
#define PS 8

// dynamic smem: 3 chunk buffers of 40960B: [AH 10240 | AL 10240 | BH 10240 | BL 10240]
// (A/B tiles are 128 rows x 40 bf16, stride 80B; 64B data + 16B pad per row)
#define GBUF   40960
#define A_LO   10240
#define B_HI   20480
#define B_LO   30720
#define CTRL_OFF 122880
#define SMEM_SZ  131072

struct Ctrl {
    const float* hl[128];
    const float* hr[128];
    const float* cl[128];
    const float* cr[128];
    int  out[128];
    int  idx[128];
};

// ------------------------- scratch (static device memory) ------------------
__device__ float g_tmp[NLE * TWO_H];
__device__ float g_hbuf[BB * LL * HH];
__device__ float g_cbuf[BB * LL * HH];
__device__ float g_node_h[BB * NN * HH];
__device__ float g_node_c[BB * NN * HH];
__device__ float g_gates[8192 * FIVE_H];           // tensor-path gate preacts (+split slabs)
__device__ float g_part[128 * FIVE_H * PS];        // small-path split-K partials
__device__ __nv_bfloat16 g_wb_hi[FIVE_H * TWO_H];  // W bf16 hi, [n][k]
__device__ __nv_bfloat16 g_wb_lo[FIVE_H * TWO_H];  // W bf16 lo, [n][k]
__device__ __nv_bfloat16 g_xa_hi[8192 * TWO_H];    // level x bf16 hi, [idx][k]
__device__ __nv_bfloat16 g_xa_lo[8192 * TWO_H];    // level x bf16 lo
__device__ float g_sum[TWO_H];
__device__ float g_sumsq[TWO_H];
__device__ int2  g_ch[BB * NN];
__device__ int   g_items[BB * NN];
__device__ int   g_lv_start[132];
__device__ int   g_maxlvl;
__device__ int   g_fin[BB];
__device__ int            g_bar_count;
__device__ volatile int   g_bar_gen;

__device__ __forceinline__ float sigf(float x) { return 1.0f / (1.0f + expf(-x)); }

__device__ __forceinline__ ull ffma2(ull x, ull w, ull a) {
    asm("fma.rn.f32x2 %0, %1, %2, %0;" : "+l"(a) : "l"(x), "l"(w));
    return a;
}
__device__ __forceinline__ ull pk2(float v) {
    ull r; asm("mov.b64 %0, {%1, %2};" : "=l"(r) : "f"(v), "f"(v)); return r;
}
__device__ __forceinline__ float2 upk(ull v) {
    float2 f; asm("mov.b64 {%0, %1}, %2;" : "=f"(f.x), "=f"(f.y) : "l"(v)); return f;
}
__device__ __forceinline__ uint s2u(const void* p) {
    uint a; asm("{ .reg .u64 t; cvta.to.shared.u64 t, %1; cvt.u32.u64 %0, t; }"
                : "=r"(a) : "l"(p));
    return a;
}

// cp.async 16B global->shared
__device__ __forceinline__ void cp16(uint dst, const void* src) {
    asm volatile("cp.async.cg.shared.global [%0], [%1], 16;" :: "r"(dst), "l"(src));
}
__device__ __forceinline__ void cp_commit() {
    asm volatile("cp.async.commit_group;" ::: "memory");
}
template <int N>
__device__ __forceinline__ void cp_wait() {
    asm volatile("cp.async.wait_group %0;" :: "n"(N) : "memory");
}

// mma.sync m16n8k16 row.col f32.bf16.bf16.f32 (base-target HMMA)
__device__ __forceinline__ void mma_bf16(float* c, uint a0, uint a1, uint a2, uint a3,
                                         uint b0, uint b1) {
    asm volatile("mma.sync.aligned.m16n8k16.row.col.f32.bf16.bf16.f32 "
                 "{%0,%1,%2,%3}, {%4,%5,%6,%7}, {%8,%9}, {%0,%1,%2,%3};"
                 : "+f"(c[0]), "+f"(c[1]), "+f"(c[2]), "+f"(c[3])
                 : "r"(a0), "r"(a1), "r"(a2), "r"(a3), "r"(b0), "r"(b1));
}

#define LDSM4(r0, r1, r2, r3, addr) asm volatile( \
    "ldmatrix.sync.aligned.m8n8.x4.shared.b16 {%0,%1,%2,%3}, [%4];" \
    : "=r"(r0), "=r"(r1), "=r"(r2), "=r"(r3) : "r"(addr))

__device__ __forceinline__ void cvt2(float a, float b, uint &hp, uint &lp) {
    __nv_bfloat16 ha = __float2bfloat16(a), hb = __float2bfloat16(b);
    float ra = a - __bfloat162float(ha);
    float rb2 = b - __bfloat162float(hb);
    __nv_bfloat16 la = __float2bfloat16(ra), lb = __float2bfloat16(rb2);
    hp = (uint)*(unsigned short*)&ha | ((uint)*(unsigned short*)&hb << 16);
    lp = (uint)*(unsigned short*)&la | ((uint)*(unsigned short*)&lb << 16);
}

__device__ __forceinline__ const float* hsrc(int b, int id) {
    return (id < 128) ? (g_hbuf + (b * LL + id) * HH)
                      : (g_node_h + (b * NN + (id - 128)) * HH);
}
__device__ __forceinline__ const float* csrc(int b, int id) {
    return (id < 128) ? (g_cbuf + (b * LL + id) * HH)
                      : (g_node_c + (b * NN + (id - 128)) * HH);
}

__device__ __forceinline__ void grid_barrier(int nblk) {
    __syncthreads();
    if (threadIdx.x == 0) {
        __threadfence();
        int gen = g_bar_gen;
        if (atomicAdd(&g_bar_count, 1) == nblk - 1) {
            g_bar_count = 0;
            __threadfence();
            g_bar_gen = gen + 1;
        } else {
            while (g_bar_gen == gen) { __nanosleep(32); }
        }
        __threadfence();
    }
    __syncthreads();
}

// ------------------- launch #1: word GEMM (f32x2) + stat zeroing ------------
__global__ __launch_bounds__(256) void word_gemm(
    const float* __restrict__ A, const float* __restrict__ Wm,
    const float* __restrict__ bias)
{
    __shared__ float As[32 * 129];
    __shared__ __align__(16) float Bs[32][64];
    const int tid = threadIdx.x;
    const int tx = tid & 15;
    const int ty = tid >> 4;
    const int rowBase = blockIdx.y * 128;
    const int colBase = blockIdx.x * 64;

    if (blockIdx.x == 0 && blockIdx.y == 0) {
        for (int i = tid; i < TWO_H; i += 256) { g_sum[i] = 0.f; g_sumsq[i] = 0.f; }
    }

    ull acc[8][2];
#pragma unroll
    for (int i = 0; i < 8; i++) { acc[i][0] = 0ull; acc[i][1] = 0ull; }

    for (int k0 = 0; k0 < EE; k0 += 32) {
#pragma unroll
        for (int i = 0; i < 4; i++) {
            int f = tid + i * 256;
            int r = f >> 3, c4 = f & 7;
            float4 v = *(const float4*)(A + (rowBase + r) * EE + k0 + c4 * 4);
            As[(c4 * 4 + 0) * 129 + r] = v.x;
            As[(c4 * 4 + 1) * 129 + r] = v.y;
            As[(c4 * 4 + 2) * 129 + r] = v.z;
            As[(c4 * 4 + 3) * 129 + r] = v.w;
        }
#pragma unroll
        for (int i = 0; i < 2; i++) {
            int f = tid + i * 256;
            int r = f >> 4, c4 = f & 15;
            *(float4*)&Bs[r][c4 * 4] =
                *(const float4*)(Wm + (k0 + r) * TWO_H + colBase + c4 * 4);
        }
        __syncthreads();
#pragma unroll 8
        for (int kk = 0; kk < 32; kk++) {
            const float* ar = As + kk * 129 + ty * 8;
            ulonglong2 w2 = *(const ulonglong2*)&Bs[kk][tx * 4];
#pragma unroll
            for (int i = 0; i < 8; i++) {
                ull xp = pk2(ar[i]);
                acc[i][0] = ffma2(xp, w2.x, acc[i][0]);
                acc[i][1] = ffma2(xp, w2.y, acc[i][1]);
            }
        }
        __syncthreads();
    }

    const int col = colBase + tx * 4;
    float2 b0 = *(const float2*)(bias + col);
    float2 b1 = *(const float2*)(bias + col + 2);
#pragma unroll
    for (int i = 0; i < 8; i++) {
        int row = rowBase + ty * 8 + i;
        float2 v0 = upk(acc[i][0]);
        float2 v1 = upk(acc[i][1]);
        v0.x += b0.x; v0.y += b0.y;
        v1.x += b1.x; v1.y += b1.y;
        *(float2*)&g_tmp[row * TWO_H + col] = v0;
        *(float2*)&g_tmp[row * TWO_H + col + 2] = v1;
    }
}

// ----- launch #2: fused bn_stats (blocks 0..1023) + wprep (1024..11263) -----
// ----- + meta tree build (block 11264)                                  -----
__global__ __launch_bounds__(256) void stats_wprep_meta(
    const float* __restrict__ W, const int* __restrict__ trans)
{
    __shared__ int cnt[132];
    __shared__ int cur[132];
    __shared__ int smax;
    const int bx = blockIdx.x;
    const int tid = threadIdx.x;

    if (bx < 1024) {
        int ch = (bx & 3) * 256 + tid;
        int rowBase = (bx >> 2) * 64;
        float s = 0.f, q = 0.f;
#pragma unroll 4
        for (int r = 0; r < 64; r++) {
            float v = g_tmp[(rowBase + r) * TWO_H + ch];
            s += v; q += v * v;
        }
        atomicAdd(&g_sum[ch], s);
        atomicAdd(&g_sumsq[ch], q);
    } else if (bx < 11264) {
        int f = (bx - 1024) * 256 + tid;       // f = k*2560 + n
        if (f < TWO_H * FIVE_H) {
            int k = f / FIVE_H, n = f - k * FIVE_H;
            float w = W[f];
            __nv_bfloat16 hb = __float2bfloat16(w);
            float rest = w - __bfloat162float(hb);
            __nv_bfloat16 lb = __float2bfloat16(rest);
            g_wb_hi[n * TWO_H + k] = hb;
            g_wb_lo[n * TWO_H + k] = lb;
        }
    } else {
        int b = tid;
        for (int i = b; i < 132; i += 256) cnt[i] = 0;
        if (b == 0) smax = 0;
        __syncthreads();
        if (b < 128) {
            int sid[130];
            int slv[130];
            int nlv[NN];
            int ptr = 0, bp = 0, n = 0;
            for (int t = 0; t < TT; t++) {
                int act = trans[b * TT + t];
                if (act == 2) {
                    sid[ptr] = bp; slv[ptr] = 0; ptr++; bp++;
                } else if (act == 3) {
                    int lv = max(slv[ptr - 2], slv[ptr - 1]) + 1;
                    g_ch[b * NN + n] = make_int2(sid[ptr - 2], sid[ptr - 1]);
                    nlv[n] = lv;
                    sid[ptr - 2] = 128 + n; slv[ptr - 2] = lv;
                    ptr--; n++;
                }
            }
            g_fin[b] = sid[0];
            int mymax = 0;
            for (int i = 0; i < n; i++) {
                atomicAdd(&cnt[nlv[i]], 1);
                mymax = max(mymax, nlv[i]);
            }
            atomicMax(&smax, mymax);
            __syncthreads();
            if (b == 0) {
                int a = 0;
                for (int lv = 0; lv <= 130; lv++) {
                    cur[lv] = a;
                    g_lv_start[lv] = a;
                    a += cnt[lv];
                }
                g_lv_start[131] = a;
                g_maxlvl = smax;
            }
            __syncthreads();
            for (int i = 0; i < n; i++) {
                int idx = atomicAdd(&cur[nlv[i]], 1);
                g_items[idx] = (b << 7) | i;
            }
        } else {
            __syncthreads();
            __syncthreads();
        }
    }
}

// ------- launch #3: bn apply with inline finalize (16 rows / thread) --------
__global__ __launch_bounds__(256) void bn_apply_fin(
    const float* __restrict__ gamma, const float* __restrict__ beta)
{
    int id = blockIdx.x * 256 + threadIdx.x;       // < 1024*1024
    int ch = id & 1023;
    int rb2 = id >> 10;
    const float invN = 1.0f / (float)NLE;
    float mean = g_sum[ch] * invN;
    float var  = g_sumsq[ch] * invN - mean * mean;
    float sc   = gamma[ch] * rsqrtf(var + 1e-5f);
    float sh   = beta[ch] - mean * sc;
#pragma unroll 4
    for (int rr = 0; rr < 16; rr++) {
        int row = rb2 * 16 + rr;
        float v = g_tmp[row * TWO_H + ch] * sc + sh;
        if (ch < HH) g_hbuf[row * HH + ch] = v;
        else         g_cbuf[row * HH + (ch - HH)] = v;
    }
}

// ------------------- launch #4: persistent level-scan kernel ----------------
extern __shared__ char dsm_raw[];

__global__ __launch_bounds__(256) void scan_kernel(
    const float* __restrict__ W, const float* __restrict__ rb, int nblk)
{
    const int tid = threadIdx.x;
    const int lane = tid & 31;
    const int wid = tid >> 5;
    const int wm = wid >> 1;           // 0..3 : warp m-block (32 rows)
    const int wn = wid & 1;            // 0..1 : warp n-block (64 cols)
    const int g = lane >> 2;           // fragment group row
    const int tig = lane & 3;          // thread-in-group

    char* base = dsm_raw;
    Ctrl* C = (Ctrl*)(base + CTRL_OFF);
    float* Xs = (float*)(base);            // small path: 16.5KB (aliases buffers)
    float* Ws = (float*)(base + 16896);    // small path: 20KB
    const uint s0 = s2u(base);

    // ldmatrix per-thread address bases (constant; depend on lane/warp only)
    const int jmat = lane >> 3, jr = lane & 7;
    uint aBase[2], bBase[4];
    {
#pragma unroll
        for (int mf = 0; mf < 2; mf++)
            aBase[mf] = s0 + (uint)((wm * 32 + mf * 16 + (jmat & 1) * 8 + jr) * 80
                                    + (jmat >> 1) * 16);
#pragma unroll
        for (int p = 0; p < 4; p++)
            bBase[p] = s0 + B_HI + (uint)((wn * 64 + (2 * p + (jmat >> 1)) * 8 + jr) * 80
                                          + (jmat & 1) * 16);
    }

    const int r2 = tid >> 1, hf = tid & 1;       // cp.async staging coords
    const uint dst_d = (uint)(r2 * 80 + hf * 32);
    const int maxlvl = g_maxlvl;

    for (int lv = 1; lv <= maxlvl; lv++) {
        const int start = g_lv_start[lv];
        const int M = g_lv_start[lv + 1] - start;
        if (M <= 0) { grid_barrier(nblk); continue; }

        if (M > 128) {
            // ======== tensor path: per-level x -> bf16 hi/lo conversion =====
            int totalc = M * 64;                 // 16 elems per work item
            for (int u = blockIdx.x * 256 + tid; u < totalc; u += nblk * 256) {
                int i = u >> 6;
                int kq = (u & 63) << 4;
                int item = g_items[start + i];
                int b = item >> 7, n = item & 127;
                int2 ch = g_ch[b * NN + n];
                const float* src = (kq < HH) ? (hsrc(b, ch.x) + kq)
                                             : (hsrc(b, ch.y) + kq - HH);
                char* dh = (char*)(g_xa_hi + i * TWO_H + kq);
                char* dl = (char*)(g_xa_lo + i * TWO_H + kq);
#pragma unroll
                for (int q = 0; q < 4; q++) {
                    float4 v = *(const float4*)(src + q * 4);
                    uint h0, h1, l0, l1;
                    cvt2(v.x, v.y, h0, l0);
                    cvt2(v.z, v.w, h1, l1);
                    *(uint2*)(dh + q * 8) = make_uint2(h0, h1);
                    *(uint2*)(dl + q * 8) = make_uint2(l0, l1);
                }
            }
            grid_barrier(nblk);

            // ======== mma units: 128m x 128n tiles, cp.async 3-stage ========
            const int mtiles = (M + 127) >> 7;
            const int tiles0 = mtiles * 20;
            int ks = 1;
            if (tiles0 * 2 <= nblk) ks = 2;     // split-K for mid-size levels
            const int cpu2 = 32 / ks;
            const int units = tiles0 * ks;

            for (int u = blockIdx.x; u < units; u += nblk) {
                const int t2 = u % tiles0;
                const int sp = u / tiles0;
                const int mt = t2 / 20;
                const int nt = t2 - mt * 20;
                const int c0 = sp * cpu2, c1 = c0 + cpu2;

                const __nv_bfloat16* sa_h0 = g_xa_hi + (size_t)(mt * 128 + r2) * TWO_H;
                const __nv_bfloat16* sa_l0 = g_xa_lo + (size_t)(mt * 128 + r2) * TWO_H;
                const __nv_bfloat16* sb_h0 = g_wb_hi + (size_t)(nt * 128 + r2) * TWO_H;
                const __nv_bfloat16* sb_l0 = g_wb_lo + (size_t)(nt * 128 + r2) * TWO_H;

                // issue first 3 stages
#pragma unroll
                for (int st = 0; st < 3; st++) {
                    int chk = c0 + st;
                    uint db = s0 + (uint)st * GBUF + dst_d;
                    int ko = chk * 32 + hf * 16;
                    cp16(db,                 sa_h0 + ko);
                    cp16(db + 16,            sa_h0 + ko + 8);
                    cp16(db + A_LO,          sa_l0 + ko);
                    cp16(db + A_LO + 16,     sa_l0 + ko + 8);
                    cp16(db + B_HI,          sb_h0 + ko);
                    cp16(db + B_HI + 16,     sb_h0 + ko + 8);
                    cp16(db + B_LO,          sb_l0 + ko);
                    cp16(db + B_LO + 16,     sb_l0 + ko + 8);
                    cp_commit();
                }

                float acc[2][8][4];
#pragma unroll
                for (int mf = 0; mf < 2; mf++)
#pragma unroll
                    for (int nf = 0; nf < 8; nf++)
#pragma unroll
                        for (int q = 0; q < 4; q++) acc[mf][nf][q] = 0.f;

                int bufi = 0;                   // (chk - c0) % 3
                for (int chk = c0; chk < c1; chk++) {
                    if (chk + 2 < c1)      cp_wait<2>();
                    else if (chk + 1 < c1) cp_wait<1>();
                    else                   cp_wait<0>();
                    __syncthreads();

                    const uint bufo = (uint)bufi * GBUF;
#pragma unroll
                    for (int half = 0; half < 2; half++) {
                        const uint kb = bufo + (uint)half * 32;
                        uint bh[8][2], bl[8][2];
#pragma unroll
                        for (int p = 0; p < 4; p++) {
                            LDSM4(bh[2 * p][0], bh[2 * p][1],
                                  bh[2 * p + 1][0], bh[2 * p + 1][1], bBase[p] + kb);
                            LDSM4(bl[2 * p][0], bl[2 * p][1],
                                  bl[2 * p + 1][0], bl[2 * p + 1][1],
                                  bBase[p] + kb + (B_LO - B_HI));
                        }
#pragma unroll
                        for (int mf = 0; mf < 2; mf++) {
                            uint a0, a1, a2, a3, l0, l1, l2, l3;
                            LDSM4(a0, a1, a2, a3, aBase[mf] + kb);
                            LDSM4(l0, l1, l2, l3, aBase[mf] + kb + A_LO);
#pragma unroll
                            for (int nf = 0; nf < 8; nf++) {
                                mma_bf16(acc[mf][nf], a0, a1, a2, a3, bh[nf][0], bh[nf][1]);
                                mma_bf16(acc[mf][nf], l0, l1, l2, l3, bh[nf][0], bh[nf][1]);
                                mma_bf16(acc[mf][nf], a0, a1, a2, a3, bl[nf][0], bl[nf][1]);
                            }
                        }
                    }
                    __syncthreads();

                    if (chk + 3 < c1) {
                        uint db = s0 + (uint)bufi * GBUF + dst_d;
                        int ko = (chk + 3) * 32 + hf * 16;
                        cp16(db,                 sa_h0 + ko);
                        cp16(db + 16,            sa_h0 + ko + 8);
                        cp16(db + A_LO,          sa_l0 + ko);
                        cp16(db + A_LO + 16,     sa_l0 + ko + 8);
                        cp16(db + B_HI,          sb_h0 + ko);
                        cp16(db + B_HI + 16,     sb_h0 + ko + 8);
                        cp16(db + B_LO,          sb_l0 + ko);
                        cp16(db + B_LO + 16,     sb_l0 + ko + 8);
                        cp_commit();
                    }
                    bufi = (bufi == 2) ? 0 : bufi + 1;
                }

                // write accumulators (split slab sp*2048 rows)
#pragma unroll
                for (int mf = 0; mf < 2; mf++) {
                    int row = wm * 32 + mf * 16 + g;
                    int gi = sp * 2048 + mt * 128 + row;
                    float* dst0 = g_gates + (size_t)gi * FIVE_H;
#pragma unroll
                    for (int nf = 0; nf < 8; nf++) {
                        int col = nt * 128 + wn * 64 + nf * 8 + 2 * tig;
                        *(float2*)(dst0 + col) =
                            make_float2(acc[mf][nf][0], acc[mf][nf][1]);
                        *(float2*)(dst0 + 8 * FIVE_H + col) =
                            make_float2(acc[mf][nf][2], acc[mf][nf][3]);
                    }
                }
            }
            grid_barrier(nblk);

            // epilogue: sum ks partials + bias + TreeLSTM
            for (int f = blockIdx.x * 256 + tid; f < M * HH; f += nblk * 256) {
                int j = f & 511, i = f >> 9;
                int item = g_items[start + i];
                int b = item >> 7, n = item & 127;
                int2 ch = g_ch[b * NN + n];
                float ga[5];
#pragma unroll
                for (int gg3 = 0; gg3 < 5; gg3++) {
                    float s = g_gates[(size_t)i * FIVE_H + gg3 * HH + j];
                    if (ks == 2)
                        s += g_gates[(size_t)(2048 + i) * FIVE_H + gg3 * HH + j];
                    ga[gg3] = s + rb[gg3 * HH + j];
                }
                float cl = csrc(b, ch.x)[j];
                float cr = csrc(b, ch.y)[j];
                float c = sigf(ga[1]) * cl + sigf(ga[2]) * cr + sigf(ga[0]) * tanhf(ga[4]);
                float h = sigf(ga[3]) * tanhf(c);
                int o = b * NN + n;
                g_node_h[o * HH + j] = h;
                g_node_c[o * HH + j] = c;
            }
            grid_barrier(nblk);
        } else {
            // ================= small path: FFMA2 split-K ====================
            const int base_tiles = 16;
            int sv = 1;
            while (sv < PS && base_tiles * (sv << 1) <= nblk) sv <<= 1;
            const int cpu = 32 / sv;
            const int units = base_tiles * sv;
            const int ng = tid >> 3, jg = tid & 7;

            for (int u = blockIdx.x; u < units; u += nblk) {
                const int tile = u % base_tiles;
                const int split = u / base_tiles;
                const int jt = tile & 15;
                const int c0 = split * cpu, c1 = c0 + cpu;

                if (tid < 128) {
                    int gi = start + tid;
                    bool valid = gi < start + M;
                    int item = g_items[valid ? gi : start];
                    int b = item >> 7, n = item & 127;
                    int2 ch = g_ch[b * NN + n];
                    C->hl[tid] = hsrc(b, ch.x);
                    C->hr[tid] = hsrc(b, ch.y);
                    C->cl[tid] = csrc(b, ch.x);
                    C->cr[tid] = csrc(b, ch.y);
                    C->out[tid] = valid ? (b * NN + n) : -1;
                    C->idx[tid] = valid ? tid : -1;
                }
                __syncthreads();

                ull acc[4][2][5];
#pragma unroll
                for (int s = 0; s < 4; s++)
#pragma unroll
                    for (int p = 0; p < 2; p++)
#pragma unroll
                        for (int gg2 = 0; gg2 < 5; gg2++) acc[s][p][gg2] = 0ull;

                float4 xr[4];
                float4 wr[5];
                {
                    const int kc0 = c0 * 32;
                    const bool left = kc0 < HH;
                    const int koff = left ? kc0 : (kc0 - HH);
#pragma unroll
                    for (int i = 0; i < 4; i++) {
                        int f = tid + i * 256;
                        int r = f >> 3, c4 = f & 7;
                        const float* bp2 = (left ? C->hl[r] : C->hr[r]) + koff;
                        xr[i] = *(const float4*)(bp2 + c4 * 4);
                    }
#pragma unroll
                    for (int i = 0; i < 5; i++) {
                        int f4 = tid + i * 256;
                        int c4 = f4 & 7, gg2 = (f4 >> 3) % 5, k = f4 / 40;
                        wr[i] = *(const float4*)(W + (kc0 + k) * FIVE_H + gg2 * HH + jt * 32 + c4 * 4);
                    }
                }

                for (int chk = c0; chk < c1; chk++) {
#pragma unroll
                    for (int i = 0; i < 4; i++) {
                        int f = tid + i * 256;
                        int r = f >> 3, c4 = f & 7;
                        Xs[(c4 * 4 + 0) * 129 + r] = xr[i].x;
                        Xs[(c4 * 4 + 1) * 129 + r] = xr[i].y;
                        Xs[(c4 * 4 + 2) * 129 + r] = xr[i].z;
                        Xs[(c4 * 4 + 3) * 129 + r] = xr[i].w;
                    }
#pragma unroll
                    for (int i = 0; i < 5; i++)
                        *(float4*)&Ws[(tid + i * 256) * 4] = wr[i];
                    __syncthreads();

                    if (chk + 1 < c1) {
                        const int kc0 = (chk + 1) * 32;
                        const bool left = kc0 < HH;
                        const int koff = left ? kc0 : (kc0 - HH);
#pragma unroll
                        for (int i = 0; i < 4; i++) {
                            int f = tid + i * 256;
                            int r = f >> 3, c4 = f & 7;
                            const float* bp2 = (left ? C->hl[r] : C->hr[r]) + koff;
                            xr[i] = *(const float4*)(bp2 + c4 * 4);
                        }
#pragma unroll
                        for (int i = 0; i < 5; i++) {
                            int f4 = tid + i * 256;
                            int c4 = f4 & 7, gg2 = (f4 >> 3) % 5, k = f4 / 40;
                            wr[i] = *(const float4*)(W + (kc0 + k) * FIVE_H + gg2 * HH + jt * 32 + c4 * 4);
                        }
                    }

#pragma unroll 8
                    for (int k = 0; k < 32; k++) {
                        const float* xrow = Xs + k * 129 + ng * 4;
                        ull xp0 = pk2(xrow[0]);
                        ull xp1 = pk2(xrow[1]);
                        ull xp2 = pk2(xrow[2]);
                        ull xp3 = pk2(xrow[3]);
#pragma unroll
                        for (int gg2 = 0; gg2 < 5; gg2++) {
                            ulonglong2 w = *(const ulonglong2*)&Ws[(k * 5 + gg2) * 32 + jg * 4];
                            acc[0][0][gg2] = ffma2(xp0, w.x, acc[0][0][gg2]);
                            acc[0][1][gg2] = ffma2(xp0, w.y, acc[0][1][gg2]);
                            acc[1][0][gg2] = ffma2(xp1, w.x, acc[1][0][gg2]);
                            acc[1][1][gg2] = ffma2(xp1, w.y, acc[1][1][gg2]);
                            acc[2][0][gg2] = ffma2(xp2, w.x, acc[2][0][gg2]);
                            acc[2][1][gg2] = ffma2(xp2, w.y, acc[2][1][gg2]);
                            acc[3][0][gg2] = ffma2(xp3, w.x, acc[3][0][gg2]);
                            acc[3][1][gg2] = ffma2(xp3, w.y, acc[3][1][gg2]);
                        }
                    }
                    __syncthreads();
                }

                if (sv == 1) {
#pragma unroll
                    for (int s = 0; s < 4; s++) {
                        int r = ng * 4 + s;
                        int o = C->out[r];
                        if (o < 0) continue;
                        const float* clp = C->cl[r];
                        const float* crp = C->cr[r];
#pragma unroll
                        for (int p = 0; p < 2; p++) {
                            int col = jt * 32 + jg * 4 + p * 2;
                            float2 vi  = upk(acc[s][p][0]);
                            float2 vfl = upk(acc[s][p][1]);
                            float2 vfr = upk(acc[s][p][2]);
                            float2 vo  = upk(acc[s][p][3]);
                            float2 vg  = upk(acc[s][p][4]);
                            float2 bi  = *(const float2*)(rb + 0 * HH + col);
                            float2 bfl = *(const float2*)(rb + 1 * HH + col);
                            float2 bfr = *(const float2*)(rb + 2 * HH + col);
                            float2 bo  = *(const float2*)(rb + 3 * HH + col);
                            float2 bg  = *(const float2*)(rb + 4 * HH + col);
                            float2 cl = *(const float2*)(clp + col);
                            float2 cr = *(const float2*)(crp + col);
                            float2 c, h;
                            c.x = sigf(vfl.x + bfl.x) * cl.x + sigf(vfr.x + bfr.x) * cr.x
                                + sigf(vi.x + bi.x) * tanhf(vg.x + bg.x);
                            c.y = sigf(vfl.y + bfl.y) * cl.y + sigf(vfr.y + bfr.y) * cr.y
                                + sigf(vi.y + bi.y) * tanhf(vg.y + bg.y);
                            h.x = sigf(vo.x + bo.x) * tanhf(c.x);
                            h.y = sigf(vo.y + bo.y) * tanhf(c.y);
                            *(float2*)&g_node_h[o * HH + col] = h;
                            *(float2*)&g_node_c[o * HH + col] = c;
                        }
                    }
                } else {
#pragma unroll
                    for (int s = 0; s < 4; s++) {
                        int r = ng * 4 + s;
                        int idx = C->idx[r];
                        if (idx < 0) continue;
#pragma unroll
                        for (int p = 0; p < 2; p++) {
                            int col = jt * 32 + jg * 4 + p * 2;
#pragma unroll
                            for (int gg2 = 0; gg2 < 5; gg2++) {
                                float2 v = upk(acc[s][p][gg2]);
                                int bi2 = (idx * FIVE_H + gg2 * HH + col) * PS + split;
                                g_part[bi2] = v.x;
                                g_part[bi2 + PS] = v.y;
                            }
                        }
                    }
                }
                __syncthreads();
            }
            grid_barrier(nblk);

            if (sv > 1) {
                for (int f = blockIdx.x * 256 + tid; f < M * HH; f += nblk * 256) {
                    int j = f & 511, i = f >> 9;
                    int item = g_items[start + i];
                    int b = item >> 7, n = item & 127;
                    int2 ch = g_ch[b * NN + n];
                    float ga[5];
#pragma unroll
                    for (int gg2 = 0; gg2 < 5; gg2++) {
                        int bb2 = (i * FIVE_H + gg2 * HH + j) * PS;
                        float s = 0.f;
                        for (int t = 0; t < sv; t++) s += g_part[bb2 + t];
                        ga[gg2] = s + rb[gg2 * HH + j];
                    }
                    float cl = csrc(b, ch.x)[j];
                    float cr = csrc(b, ch.y)[j];
                    float c = sigf(ga[1]) * cl + sigf(ga[2]) * cr + sigf(ga[0]) * tanhf(ga[4]);
                    float h = sigf(ga[3]) * tanhf(c);
                    int o = b * NN + n;
                    g_node_h[o * HH + j] = h;
                    g_node_c[o * HH + j] = c;
                }
                grid_barrier(nblk);
            }
        }
    }
}

// ------------------------- launch #5: final readout --------------------------
__global__ void final_kernel(float* __restrict__ out)
{
    int idx = blockIdx.x * blockDim.x + threadIdx.x;
    if (idx >= BB * HH) return;
    int b = idx >> 9;
    int j = idx & 511;
    int root = g_fin[b] - 128;
    out[idx] = g_node_h[(b * NN + root) * HH + j];
}

// ------------------------- launch -------------------------------------------
extern "C" void kernel_launch(void* const* d_in, const int* in_sizes, int n_in,
                              void* d_out, int out_size)
{
    const float* sentence    = (const float*)d_in[0];
    const int*   transitions = (const int*)  d_in[1];
    const float* word_W      = (const float*)d_in[2];
    const float* word_b      = (const float*)d_in[3];
    const float* bn_gamma    = (const float*)d_in[4];
    const float* bn_beta     = (const float*)d_in[5];
    const float* reduce_W    = (const float*)d_in[6];
    const float* reduce_b    = (const float*)d_in[7];
    float* out = (float*)d_out;

    int dev = 0, nsm = 148;
    cudaGetDevice(&dev);
    cudaDeviceGetAttribute(&nsm, cudaDevAttrMultiProcessorCount, dev);
    cudaFuncSetAttribute(scan_kernel, cudaFuncAttributeMaxDynamicSharedMemorySize, SMEM_SZ);

    // #1
    word_gemm<<<dim3(TWO_H / 64, NLE / 128), 256>>>(sentence, word_W, word_b);
    // #2 : bn_stats (1024) + wprep (10240) + meta (1)
    stats_wprep_meta<<<11265, 256>>>(reduce_W, transitions);
    // #3
    bn_apply_fin<<<4096, 256>>>(bn_gamma, bn_beta);
    // #4 : the kernel we want ncu to capture
    scan_kernel<<<nsm, 256, SMEM_SZ>>>(reduce_W, reduce_b, nsm);
    // #5
    final_kernel<<<(BB * HH + 255) / 256, 256>>>(out);
}